// round 11
// baseline (speedup 1.0000x reference)
#include <cuda_runtime.h>
#include <math.h>
#include <stdint.h>

#define H     128
#define NB    16384
#define NPG   26
#define EPG   52
#define NCL   7
#define NTOT  (NB*NPG)      // 425984
#define NEDGE (NB*EPG)      // 851968

// ------------- scratch: device globals (no runtime allocation) -------------
__device__ float g_h[NTOT*H];        // node features (in-place per layer)
__device__ float g_mean[NTOT*H];     // neighbor means
__device__ float g_t[NTOT*14];       // [n*14+c]: c<7 -> h@aWl, c>=7 -> h@aWr
__device__ float g_x2[NB*NCL*H];     // pooled cluster features (in-place)
__device__ float g_pm[NB*H];         // per-graph mean of clusters
__device__ float g_linkpart[NB];
__device__ float g_entpart[NB];

// ---- cp.async helpers ----
#define CP_ASYNC16(dst, src) \
    asm volatile("cp.async.cg.shared.global [%0], [%1], 16;\n" :: "r"(dst), "l"(src))
#define CP_COMMIT() asm volatile("cp.async.commit_group;\n" ::: "memory")
#define CP_WAIT(n)  asm volatile("cp.async.wait_group %0;\n" :: "n"(n) : "memory")

// ================= K1: fused atom encoder + layer-0 neighbor mean =================
__global__ __launch_bounds__(128)
void k_encagg(const int* __restrict__ x, const float* __restrict__ emb,
              const int* __restrict__ ei) {
    __shared__ float sh[NPG * H];
    __shared__ int   sx[NPG * 9];
    __shared__ int   se[EPG], sde[EPG], sdeg[NPG], sstart[NPG+1], soffs[NPG], ssrt[EPG];
    __shared__ float srdeg[NPG];
    const int g = blockIdx.x, tid = threadIdx.x;
    for (int i = tid; i < NPG*9; i += 128) sx[i] = x[(size_t)g*NPG*9 + i];
    if (tid < NPG) sdeg[tid] = 0;
    if (tid < EPG) {
        se[tid]  = ei[(size_t)g*EPG + tid]                 - g*NPG;
        sde[tid] = ei[(size_t)NEDGE + (size_t)g*EPG + tid] - g*NPG;
    }
    __syncthreads();
    if (tid < EPG) atomicAdd(&sdeg[sde[tid]], 1);
    __syncthreads();
    if (tid == 0) {
        int acc = 0;
        #pragma unroll
        for (int n = 0; n < NPG; n++) { sstart[n] = acc; acc += sdeg[n]; }
        sstart[NPG] = acc;
    }
    if (tid < NPG) srdeg[tid] = 1.f / fmaxf((float)sdeg[tid], 1.f);
    __syncthreads();
    if (tid < NPG) soffs[tid] = sstart[tid];
    __syncthreads();
    if (tid < EPG) {
        int pos = atomicAdd(&soffs[sde[tid]], 1);
        ssrt[pos] = se[tid];
    }
    float* hg = g_h + (size_t)g * NPG * H;
    for (int n = 0; n < NPG; n++) {
        float acc = 0.f;
        #pragma unroll
        for (int f = 0; f < 9; f++) {
            int v = sx[n*9 + f];
            acc += __ldg(&emb[((size_t)f*119 + v)*128 + tid]);
        }
        sh[n*H + tid] = acc;
        hg[(size_t)n*H + tid] = acc;
    }
    __syncthreads();
    float* mg = g_mean + (size_t)g * NPG * H;
    #pragma unroll 2
    for (int n = 0; n < NPG; n++) {
        float acc = 0.f;
        int b = sstart[n], e2 = sstart[n+1];
        for (int j = b; j < e2; j++) acc += sh[ssrt[j]*H + tid];
        mg[(size_t)n*H + tid] = acc * srdeg[n];
    }
}

// ================= K2: neighbor-mean via CSR counting sort (R7-proven) =================
__global__ __launch_bounds__(128)
void k_agg2(const int* __restrict__ ei) {
    __shared__ float sh[NPG * H];
    __shared__ int   se[EPG], sde[EPG], sdeg[NPG], sstart[NPG+1], soffs[NPG], ssrt[EPG];
    __shared__ float srdeg[NPG];
    const int g = blockIdx.x, tid = threadIdx.x;
    const float* hg = g_h + (size_t)g * NPG * H;
    for (int i = tid; i < NPG*32; i += 128)
        *(float4*)&sh[i*4] = *(const float4*)(hg + (size_t)i*4);
    if (tid < NPG) sdeg[tid] = 0;
    __syncthreads();
    if (tid < EPG) {
        int s = ei[(size_t)g*EPG + tid]                 - g*NPG;
        int d = ei[(size_t)NEDGE + (size_t)g*EPG + tid] - g*NPG;
        se[tid] = s; sde[tid] = d;
        atomicAdd(&sdeg[d], 1);
    }
    __syncthreads();
    if (tid == 0) {
        int acc = 0;
        #pragma unroll
        for (int n = 0; n < NPG; n++) { sstart[n] = acc; acc += sdeg[n]; }
        sstart[NPG] = acc;
    }
    if (tid < NPG) srdeg[tid] = 1.f / fmaxf((float)sdeg[tid], 1.f);
    __syncthreads();
    if (tid < NPG) soffs[tid] = sstart[tid];
    __syncthreads();
    if (tid < EPG) {
        int pos = atomicAdd(&soffs[sde[tid]], 1);
        ssrt[pos] = se[tid];
    }
    __syncthreads();
    float* mg = g_mean + (size_t)g * NPG * H;
    const int c = tid;
    #pragma unroll 2
    for (int n = 0; n < NPG; n++) {
        float acc = 0.f;
        int b = sstart[n], e2 = sstart[n+1];
        for (int j = b; j < e2; j++) acc += sh[ssrt[j]*H + c];
        mg[(size_t)n*H + c] = acc * srdeg[n];
    }
}

// ================= tf32 mma.sync helper (verified layout) =================
__device__ __forceinline__ void mma_tf32(float* d, const uint32_t* a,
                                         uint32_t b0, uint32_t b1) {
    asm volatile(
        "mma.sync.aligned.m16n8k8.row.col.f32.tf32.tf32.f32 "
        "{%0,%1,%2,%3}, {%4,%5,%6,%7}, {%8,%9}, {%0,%1,%2,%3};\n"
        : "+f"(d[0]), "+f"(d[1]), "+f"(d[2]), "+f"(d[3])
        : "r"(a[0]), "r"(a[1]), "r"(a[2]), "r"(a[3]), "r"(b0), "r"(b1));
}

#define WPITCH 132
#define TPITCH 17
#define WP2    132
#define AP2    36
#define PIPE_FLOATS (2*32*WP2 + 2*128*AP2)   // 17664 floats = 70656 B

// ================= K3a: pipelined tensor-core GEMM (512 threads, warp tile 32x32) =================
template<int RELU, int POOLED>
__global__ __launch_bounds__(512, 2)
void k_gemm_pipe(const float* __restrict__ Wl, const float* __restrict__ Wr,
                 const float* __restrict__ bl,
                 const float* __restrict__ bng, const float* __restrict__ bnb,
                 const float* __restrict__ bnm, const float* __restrict__ bnv)
{
    extern __shared__ float smem[];
    float* sWb0 = smem;
    float* sWb1 = smem + 32*WP2;
    float* sAb0 = smem + 2*32*WP2;
    float* sAb1 = smem + 2*32*WP2 + 128*AP2;
    __shared__ float sscale[128], sshift[128];

    const int tid  = threadIdx.x;
    const int row0 = blockIdx.x * 128;
    const float* Am = POOLED ? g_pm : g_mean;
    float*       Ah = POOLED ? g_x2 : g_h;

    if (tid < 128) {
        float sc = bng[tid] * rsqrtf(bnv[tid] + 1e-5f);
        sscale[tid] = sc;
        sshift[tid] = bnb[tid] + sc * (bl[tid] - bnm[tid]);
    }

    const int lane = tid & 31, warp = tid >> 5;   // 16 warps
    const int gid = lane >> 2, tig = lane & 3;
    const int wr0 = (warp & 3) * 32;
    const int wc0 = (warp >> 2) * 32;
    float d[2][4][4] = {};

    auto issue = [&](int ch, float* sA, float* sW) {
        #pragma unroll
        for (int v = 0; v < 2; v++) {
            int i  = tid + v*512;              // 0..1023
            int r  = i >> 3, c4 = (i & 7) * 4;
            int gk = ch*32 + c4;
            int grow = row0 + r;
            const float* ap;
            if (gk < 128) {
                int mrow = POOLED ? (grow / 7) : grow;
                ap = Am + (size_t)mrow*128 + gk;
            } else {
                ap = Ah + (size_t)grow*128 + (gk - 128);
            }
            uint32_t dst = (uint32_t)__cvta_generic_to_shared(&sA[r*AP2 + c4]);
            CP_ASYNC16(dst, ap);
        }
        #pragma unroll
        for (int v = 0; v < 2; v++) {
            int i  = tid + v*512;
            int r  = i >> 5, c4 = (i & 31) * 4;
            int gk = ch*32 + r;
            const float* wp = (gk < 128) ? (Wl + (size_t)gk*128 + c4)
                                         : (Wr + (size_t)(gk - 128)*128 + c4);
            uint32_t dst = (uint32_t)__cvta_generic_to_shared(&sW[r*WP2 + c4]);
            CP_ASYNC16(dst, wp);
        }
        CP_COMMIT();
    };

    issue(0, sAb0, sWb0);
    #pragma unroll
    for (int ch = 0; ch < 8; ch++) {
        if (ch < 7) issue(ch + 1, ((ch+1) & 1) ? sAb1 : sAb0,
                                   ((ch+1) & 1) ? sWb1 : sWb0);
        if (ch < 7) { CP_WAIT(1); } else { CP_WAIT(0); }
        __syncthreads();
        const float* sA = (ch & 1) ? sAb1 : sAb0;
        const float* sW = (ch & 1) ? sWb1 : sWb0;
        #pragma unroll
        for (int ks = 0; ks < 4; ks++) {
            const int kk = ks * 8;
            uint32_t a[2][4];
            #pragma unroll
            for (int mi = 0; mi < 2; mi++) {
                const float* ap = sA + (wr0 + mi*16 + gid)*AP2 + kk + tig;
                a[mi][0] = __float_as_uint(ap[0]);
                a[mi][1] = __float_as_uint(ap[8*AP2]);
                a[mi][2] = __float_as_uint(ap[4]);
                a[mi][3] = __float_as_uint(ap[8*AP2 + 4]);
            }
            const float* bp = sW + (kk + tig)*WP2 + wc0 + gid;
            #pragma unroll
            for (int nj = 0; nj < 4; nj++) {
                uint32_t b0 = __float_as_uint(bp[nj*8]);
                uint32_t b1 = __float_as_uint(bp[nj*8 + 4*WP2]);
                mma_tf32(d[0][nj], a[0], b0, b1);
                mma_tf32(d[1][nj], a[1], b0, b1);
            }
        }
        __syncthreads();
    }

    #pragma unroll
    for (int mi = 0; mi < 2; mi++)
        #pragma unroll
        for (int half = 0; half < 2; half++) {
            const int row = wr0 + mi*16 + gid + half*8;
            float* orow = Ah + (size_t)(row0 + row) * 128;
            #pragma unroll
            for (int nj = 0; nj < 4; nj++) {
                const int col = wc0 + nj*8 + tig*2;
                float2 res = *(float2*)(orow + col);
                float v0 = d[mi][nj][half*2 + 0] * sscale[col]     + sshift[col];
                float v1 = d[mi][nj][half*2 + 1] * sscale[col + 1] + sshift[col + 1];
                if (RELU) { v0 = fmaxf(v0, 0.f); v1 = fmaxf(v1, 0.f); }
                *(float2*)(orow + col) = make_float2(v0 + res.x, v1 + res.y);
            }
        }
}

// ================= K3b: pipelined GEMM + fused T epilogue (512 threads, li=1) =================
__global__ __launch_bounds__(512, 2)
void k_gemm_pipeT(const float* __restrict__ Wl, const float* __restrict__ Wr,
                  const float* __restrict__ bl,
                  const float* __restrict__ bng, const float* __restrict__ bnb,
                  const float* __restrict__ bnm, const float* __restrict__ bnv,
                  const float* __restrict__ aWl, const float* __restrict__ aWr)
{
    extern __shared__ float smem[];
    float* sWb0 = smem;
    float* sWb1 = smem + 32*WP2;
    float* sAb0 = smem + 2*32*WP2;
    float* sAb1 = smem + 2*32*WP2 + 128*AP2;
    float* sHf  = smem;                        // overlay after main loop
    __shared__ float sscale[128], sshift[128];
    __shared__ float sW2[128*TPITCH];

    const int tid  = threadIdx.x;
    const int row0 = blockIdx.x * 128;

    if (tid < 128) {
        float sc = bng[tid] * rsqrtf(bnv[tid] + 1e-5f);
        sscale[tid] = sc;
        sshift[tid] = bnb[tid] + sc * (bl[tid] - bnm[tid]);
    }
    for (int i = tid; i < 128*16; i += 512) {
        int k = i >> 4, c = i & 15;
        float v = 0.f;
        if (c < 7)       v = aWl[k*NCL + c];
        else if (c < 14) v = aWr[k*NCL + (c - 7)];
        sW2[k*TPITCH + c] = v;
    }

    const int lane = tid & 31, warp = tid >> 5;
    const int gid = lane >> 2, tig = lane & 3;
    const int wr0 = (warp & 3) * 32;
    const int wc0 = (warp >> 2) * 32;
    float d[2][4][4] = {};

    auto issue = [&](int ch, float* sA, float* sW) {
        #pragma unroll
        for (int v = 0; v < 2; v++) {
            int i  = tid + v*512;
            int r  = i >> 3, c4 = (i & 7) * 4;
            int gk = ch*32 + c4;
            int grow = row0 + r;
            const float* ap = (gk < 128) ? (g_mean + (size_t)grow*128 + gk)
                                         : (g_h    + (size_t)grow*128 + (gk - 128));
            uint32_t dst = (uint32_t)__cvta_generic_to_shared(&sA[r*AP2 + c4]);
            CP_ASYNC16(dst, ap);
        }
        #pragma unroll
        for (int v = 0; v < 2; v++) {
            int i  = tid + v*512;
            int r  = i >> 5, c4 = (i & 31) * 4;
            int gk = ch*32 + r;
            const float* wp = (gk < 128) ? (Wl + (size_t)gk*128 + c4)
                                         : (Wr + (size_t)(gk - 128)*128 + c4);
            uint32_t dst = (uint32_t)__cvta_generic_to_shared(&sW[r*WP2 + c4]);
            CP_ASYNC16(dst, wp);
        }
        CP_COMMIT();
    };

    issue(0, sAb0, sWb0);
    #pragma unroll
    for (int ch = 0; ch < 8; ch++) {
        if (ch < 7) issue(ch + 1, ((ch+1) & 1) ? sAb1 : sAb0,
                                   ((ch+1) & 1) ? sWb1 : sWb0);
        if (ch < 7) { CP_WAIT(1); } else { CP_WAIT(0); }
        __syncthreads();
        const float* sA = (ch & 1) ? sAb1 : sAb0;
        const float* sW = (ch & 1) ? sWb1 : sWb0;
        #pragma unroll
        for (int ks = 0; ks < 4; ks++) {
            const int kk = ks * 8;
            uint32_t a[2][4];
            #pragma unroll
            for (int mi = 0; mi < 2; mi++) {
                const float* ap = sA + (wr0 + mi*16 + gid)*AP2 + kk + tig;
                a[mi][0] = __float_as_uint(ap[0]);
                a[mi][1] = __float_as_uint(ap[8*AP2]);
                a[mi][2] = __float_as_uint(ap[4]);
                a[mi][3] = __float_as_uint(ap[8*AP2 + 4]);
            }
            const float* bp = sW + (kk + tig)*WP2 + wc0 + gid;
            #pragma unroll
            for (int nj = 0; nj < 4; nj++) {
                uint32_t b0 = __float_as_uint(bp[nj*8]);
                uint32_t b1 = __float_as_uint(bp[nj*8 + 4*WP2]);
                mma_tf32(d[0][nj], a[0], b0, b1);
                mma_tf32(d[1][nj], a[1], b0, b1);
            }
        }
        __syncthreads();
    }

    // epilogue: bn + relu + residual; write global AND the sHf overlay
    #pragma unroll
    for (int mi = 0; mi < 2; mi++)
        #pragma unroll
        for (int half = 0; half < 2; half++) {
            const int row = wr0 + mi*16 + gid + half*8;
            float* orow = g_h + (size_t)(row0 + row) * 128;
            #pragma unroll
            for (int nj = 0; nj < 4; nj++) {
                const int col = wc0 + nj*8 + tig*2;
                float2 res = *(float2*)(orow + col);
                float v0 = d[mi][nj][half*2 + 0] * sscale[col]     + sshift[col];
                float v1 = d[mi][nj][half*2 + 1] * sscale[col + 1] + sshift[col + 1];
                v0 = fmaxf(v0, 0.f); v1 = fmaxf(v1, 0.f);
                v0 += res.x; v1 += res.y;
                *(float2*)(orow + col) = make_float2(v0, v1);
                sHf[row*WPITCH + col]     = v0;
                sHf[row*WPITCH + col + 1] = v1;
            }
        }

    __syncthreads();
    // T = h_final(sHf) @ W2(sW2, 128x16); warps 0..7, 16 rows each
    if (warp < 8) {
        float dt[2][4] = {};
        #pragma unroll
        for (int ks = 0; ks < 16; ks++) {
            const int kk = ks * 8;
            uint32_t a[4];
            const float* ap = sHf + (warp*16 + gid)*WPITCH + kk + tig;
            a[0] = __float_as_uint(ap[0]);
            a[1] = __float_as_uint(ap[8*WPITCH]);
            a[2] = __float_as_uint(ap[4]);
            a[3] = __float_as_uint(ap[8*WPITCH + 4]);
            #pragma unroll
            for (int nt = 0; nt < 2; nt++) {
                uint32_t b0 = __float_as_uint(sW2[(kk + tig)*TPITCH     + nt*8 + gid]);
                uint32_t b1 = __float_as_uint(sW2[(kk + tig + 4)*TPITCH + nt*8 + gid]);
                mma_tf32(dt[nt], a, b0, b1);
            }
        }
        #pragma unroll
        for (int nt = 0; nt < 2; nt++)
            #pragma unroll
            for (int half = 0; half < 2; half++) {
                const int row = warp*16 + gid + half*8;
                const int col = nt*8 + tig*2;
                float* trow = g_t + (size_t)(row0 + row) * 14;
                if (col < 14)     trow[col]     = dt[nt][half*2 + 0];
                if (col + 1 < 14) trow[col + 1] = dt[nt][half*2 + 1];
            }
    }
}

// ================= K4: per-graph logits-agg + softmax + pooling + losses + pm =================
__global__ void k_pool(const int* __restrict__ ei, const float* __restrict__ abl) {
    __shared__ float sh[NPG * H];
    __shared__ float t1[NPG*NCL], t2[NPG*NCL], ssl[NPG*NCL], sd[NPG*NCL];
    __shared__ float adj[NPG * NPG];
    __shared__ int   se[EPG], de[EPG], degi[NPG];
    __shared__ float red[128], red2[128];
    const int g = blockIdx.x, tid = threadIdx.x;  // 128
    const float* hg = g_h + (size_t)g * NPG * H;
    for (int i = tid; i < NPG * H; i += 128) sh[i] = hg[i];
    for (int i = tid; i < NPG * 14; i += 128) {
        int n = i / 14, c = i - n*14;
        float v = g_t[(size_t)g*NPG*14 + i];
        if (c < 7) t1[n*7 + c] = v; else t2[n*7 + (c-7)] = v;
    }
    for (int i = tid; i < NPG * NPG; i += 128) adj[i] = 0.f;
    for (int i = tid; i < NPG * NCL; i += 128) ssl[i] = 0.f;
    if (tid < NPG) degi[tid] = 0;
    if (tid < EPG) {
        se[tid] = ei[(size_t)g*EPG + tid]                 - g*NPG;
        de[tid] = ei[(size_t)NEDGE + (size_t)g*EPG + tid] - g*NPG;
    }
    __syncthreads();
    if (tid < EPG) {
        atomicAdd(&degi[de[tid]], 1);
        atomicAdd(&adj[se[tid]*NPG + de[tid]], 1.f);
        #pragma unroll
        for (int c = 0; c < NCL; c++)
            atomicAdd(&ssl[de[tid]*NCL + c], t1[se[tid]*NCL + c]);
    }
    __syncthreads();
    for (int i = tid; i < NPG * NCL; i += 128) {
        int n = i / NCL;
        ssl[i] = ssl[i] / fmaxf((float)degi[n], 1.f) + t2[i] + abl[i - n*NCL];
    }
    __syncthreads();
    float ent_local = 0.f;
    if (tid < NPG) {
        float v[NCL], mx = -1e30f;
        #pragma unroll
        for (int c = 0; c < NCL; c++) { v[c] = ssl[tid*NCL + c]; mx = fmaxf(mx, v[c]); }
        float s = 0.f;
        #pragma unroll
        for (int c = 0; c < NCL; c++) { v[c] = expf(v[c] - mx); s += v[c]; }
        float inv = 1.f / s;
        #pragma unroll
        for (int c = 0; c < NCL; c++) {
            float p = v[c] * inv;
            sd[tid*NCL + c] = p;
            ent_local += -p * logf(p + 1e-15f);
        }
    }
    __syncthreads();
    float* x2g = g_x2 + (size_t)g * NCL * H;
    float pmsum = 0.f;
    #pragma unroll
    for (int c = 0; c < NCL; c++) {
        float a = 0.f;
        #pragma unroll
        for (int n = 0; n < NPG; n++) a += sd[n*NCL + c] * sh[n*128 + tid];
        x2g[c*128 + tid] = a;
        pmsum += a;
    }
    g_pm[(size_t)g*128 + tid] = pmsum * (1.f / 7.f);
    float link_local = 0.f;
    for (int p = tid; p < NPG * NPG; p += 128) {
        int n = p / NPG, m = p - NPG*n;
        float ss = 0.f;
        #pragma unroll
        for (int c = 0; c < NCL; c++) ss += sd[n*NCL + c] * sd[m*NCL + c];
        float dd = adj[p] - ss;
        link_local += dd * dd;
    }
    red[tid] = link_local; red2[tid] = ent_local;
    __syncthreads();
    for (int s = 64; s > 0; s >>= 1) {
        if (tid < s) { red[tid] += red[tid + s]; red2[tid] += red2[tid + s]; }
        __syncthreads();
    }
    if (tid == 0) { g_linkpart[g] = red[0]; g_entpart[g] = red2[0]; }
}

// ================= K5: per-graph mean of clusters (for li=3) =================
__global__ void k_pmean() {
    int idx = blockIdx.x * 256 + threadIdx.x;
    int g = idx >> 7, col = idx & 127;
    const float* xg = g_x2 + (size_t)g * NCL * H + col;
    float a = 0.f;
    #pragma unroll
    for (int c = 0; c < NCL; c++) a += xg[c * 128];
    g_pm[idx] = a * (1.f / 7.f);
}

// ================= K6: readout =================
__global__ void k_readout(const float* __restrict__ linW, const float* __restrict__ linb,
                          float* __restrict__ out) {
    const int g = blockIdx.x, tid = threadIdx.x;  // 128
    const float* xg = g_x2 + (size_t)g * NCL * H;
    float v = 0.f;
    #pragma unroll
    for (int c = 0; c < NCL; c++) v += xg[c * 128 + tid];
    v *= (1.f / 7.f);
    __shared__ float red[128];
    red[tid] = v * linW[tid];
    __syncthreads();
    for (int s = 64; s > 0; s >>= 1) {
        if (tid < s) red[tid] += red[tid + s];
        __syncthreads();
    }
    if (tid == 0) out[g] = 1.f / (1.f + expf(-(red[0] + linb[0])));
}

// ================= K7: deterministic loss reduction =================
__global__ void k_reduce(float* __restrict__ out) {
    __shared__ float s1[1024], s2[1024];
    const int tid = threadIdx.x;
    float a = 0.f, b = 0.f;
    for (int i = tid; i < NB; i += 1024) { a += g_linkpart[i]; b += g_entpart[i]; }
    s1[tid] = a; s2[tid] = b;
    __syncthreads();
    for (int s = 512; s > 0; s >>= 1) {
        if (tid < s) { s1[tid] += s1[tid + s]; s2[tid] += s2[tid + s]; }
        __syncthreads();
    }
    if (tid == 0) {
        out[NB]     = sqrtf(s1[0]) / 11075584.f;   // nb * 26 * 26
        out[NB + 1] = s2[0] / (float)NTOT;
    }
}

extern "C" void kernel_launch(void* const* d_in, const int* in_sizes, int n_in,
                              void* d_out, int out_size) {
    (void)in_sizes; (void)n_in; (void)out_size;
    const int*   x    = (const int*)  d_in[0];
    const int*   ei   = (const int*)  d_in[1];
    const float* emb  = (const float*)d_in[3];
    const float* cWl  = (const float*)d_in[4];
    const float* cbl  = (const float*)d_in[5];
    const float* cWr  = (const float*)d_in[6];
    const float* bng  = (const float*)d_in[7];
    const float* bnb  = (const float*)d_in[8];
    const float* bnm  = (const float*)d_in[9];
    const float* bnv  = (const float*)d_in[10];
    const float* aWl  = (const float*)d_in[11];
    const float* abl  = (const float*)d_in[12];
    const float* aWr  = (const float*)d_in[13];
    const float* linW = (const float*)d_in[14];
    const float* linb = (const float*)d_in[15];
    float* out = (float*)d_out;

    const int pipe_smem = PIPE_FLOATS * 4;   // 70656
    cudaFuncSetAttribute(k_gemm_pipe<1,0>, cudaFuncAttributeMaxDynamicSharedMemorySize, pipe_smem);
    cudaFuncSetAttribute(k_gemm_pipe<0,1>, cudaFuncAttributeMaxDynamicSharedMemorySize, pipe_smem);
    cudaFuncSetAttribute(k_gemm_pipeT, cudaFuncAttributeMaxDynamicSharedMemorySize, pipe_smem);

    // layer 0 (encoder fused with aggregation)
    k_encagg<<<NB, 128>>>(x, emb, ei);
    k_gemm_pipe<1,0><<<NTOT / 128, 512, pipe_smem>>>(
        cWl, cWr, cbl, bng, bnb, bnm, bnv);
    // layer 1 (+ fused T = h@[aWl|aWr])
    k_agg2<<<NB, 128>>>(ei);
    k_gemm_pipeT<<<NTOT / 128, 512, pipe_smem>>>(
        cWl + 16384, cWr + 16384, cbl + 128,
        bng + 128, bnb + 128, bnm + 128, bnv + 128, aWl, aWr);

    k_pool<<<NB, 128>>>(ei, abl);     // also writes g_pm (first pmean fused)

    // pooled layer 2
    k_gemm_pipe<0,1><<<NB * NCL / 128, 512, pipe_smem>>>(
        cWl + 2*16384, cWr + 2*16384, cbl + 2*128,
        bng + 2*128, bnb + 2*128, bnm + 2*128, bnv + 2*128);
    // pooled layer 3
    k_pmean<<<NB * 128 / 256, 256>>>();
    k_gemm_pipe<0,1><<<NB * NCL / 128, 512, pipe_smem>>>(
        cWl + 3*16384, cWr + 3*16384, cbl + 3*128,
        bng + 3*128, bnb + 3*128, bnm + 3*128, bnv + 3*128);

    k_readout<<<NB, 128>>>(linW, linb, out);
    k_reduce<<<1, 1024>>>(out);
}

// round 12
// speedup vs baseline: 1.0666x; 1.0666x over previous
#include <cuda_runtime.h>
#include <math.h>
#include <stdint.h>

#define H     128
#define NB    16384
#define NPG   26
#define EPG   52
#define NCL   7
#define NTOT  (NB*NPG)      // 425984
#define NEDGE (NB*EPG)      // 851968

// ------------- scratch: device globals (no runtime allocation) -------------
__device__ float g_h[NTOT*H];        // node features (in-place per layer)
__device__ float g_mean[NTOT*H];     // neighbor means
__device__ float g_t[NTOT*14];       // [n*14+c]: c<7 -> h@aWl, c>=7 -> h@aWr
__device__ float g_x2[NB*NCL*H];     // pooled cluster features (in-place)
__device__ float g_pm[NB*H];         // per-graph mean of clusters
__device__ float g_linkpart[NB];
__device__ float g_entpart[NB];

// ---- cp.async helpers ----
#define CP_ASYNC16(dst, src) \
    asm volatile("cp.async.cg.shared.global [%0], [%1], 16;\n" :: "r"(dst), "l"(src))
#define CP_COMMIT() asm volatile("cp.async.commit_group;\n" ::: "memory")
#define CP_WAIT(n)  asm volatile("cp.async.wait_group %0;\n" :: "n"(n) : "memory")

// ================= K1: fused atom encoder + layer-0 neighbor mean =================
__global__ __launch_bounds__(128)
void k_encagg(const int* __restrict__ x, const float* __restrict__ emb,
              const int* __restrict__ ei) {
    __shared__ float sh[NPG * H];
    __shared__ int   sx[NPG * 9];
    __shared__ int   se[EPG], sde[EPG], sdeg[NPG], sstart[NPG+1], soffs[NPG], ssrt[EPG];
    __shared__ float srdeg[NPG];
    const int g = blockIdx.x, tid = threadIdx.x;
    for (int i = tid; i < NPG*9; i += 128) sx[i] = x[(size_t)g*NPG*9 + i];
    if (tid < NPG) sdeg[tid] = 0;
    if (tid < EPG) {
        se[tid]  = ei[(size_t)g*EPG + tid]                 - g*NPG;
        sde[tid] = ei[(size_t)NEDGE + (size_t)g*EPG + tid] - g*NPG;
    }
    __syncthreads();
    if (tid < EPG) atomicAdd(&sdeg[sde[tid]], 1);
    __syncthreads();
    if (tid == 0) {
        int acc = 0;
        #pragma unroll
        for (int n = 0; n < NPG; n++) { sstart[n] = acc; acc += sdeg[n]; }
        sstart[NPG] = acc;
    }
    if (tid < NPG) srdeg[tid] = 1.f / fmaxf((float)sdeg[tid], 1.f);
    __syncthreads();
    if (tid < NPG) soffs[tid] = sstart[tid];
    __syncthreads();
    if (tid < EPG) {
        int pos = atomicAdd(&soffs[sde[tid]], 1);
        ssrt[pos] = se[tid];
    }
    float* hg = g_h + (size_t)g * NPG * H;
    for (int n = 0; n < NPG; n++) {
        float acc = 0.f;
        #pragma unroll
        for (int f = 0; f < 9; f++) {
            int v = sx[n*9 + f];
            acc += __ldg(&emb[((size_t)f*119 + v)*128 + tid]);
        }
        sh[n*H + tid] = acc;
        hg[(size_t)n*H + tid] = acc;
    }
    __syncthreads();
    float* mg = g_mean + (size_t)g * NPG * H;
    #pragma unroll 2
    for (int n = 0; n < NPG; n++) {
        float acc = 0.f;
        int b = sstart[n], e2 = sstart[n+1];
        for (int j = b; j < e2; j++) acc += sh[ssrt[j]*H + tid];
        mg[(size_t)n*H + tid] = acc * srdeg[n];
    }
}

// ================= K2: neighbor-mean via CSR counting sort (R7-proven) =================
__global__ __launch_bounds__(128)
void k_agg2(const int* __restrict__ ei) {
    __shared__ float sh[NPG * H];
    __shared__ int   se[EPG], sde[EPG], sdeg[NPG], sstart[NPG+1], soffs[NPG], ssrt[EPG];
    __shared__ float srdeg[NPG];
    const int g = blockIdx.x, tid = threadIdx.x;
    const float* hg = g_h + (size_t)g * NPG * H;
    for (int i = tid; i < NPG*32; i += 128)
        *(float4*)&sh[i*4] = *(const float4*)(hg + (size_t)i*4);
    if (tid < NPG) sdeg[tid] = 0;
    __syncthreads();
    if (tid < EPG) {
        int s = ei[(size_t)g*EPG + tid]                 - g*NPG;
        int d = ei[(size_t)NEDGE + (size_t)g*EPG + tid] - g*NPG;
        se[tid] = s; sde[tid] = d;
        atomicAdd(&sdeg[d], 1);
    }
    __syncthreads();
    if (tid == 0) {
        int acc = 0;
        #pragma unroll
        for (int n = 0; n < NPG; n++) { sstart[n] = acc; acc += sdeg[n]; }
        sstart[NPG] = acc;
    }
    if (tid < NPG) srdeg[tid] = 1.f / fmaxf((float)sdeg[tid], 1.f);
    __syncthreads();
    if (tid < NPG) soffs[tid] = sstart[tid];
    __syncthreads();
    if (tid < EPG) {
        int pos = atomicAdd(&soffs[sde[tid]], 1);
        ssrt[pos] = se[tid];
    }
    __syncthreads();
    float* mg = g_mean + (size_t)g * NPG * H;
    const int c = tid;
    #pragma unroll 2
    for (int n = 0; n < NPG; n++) {
        float acc = 0.f;
        int b = sstart[n], e2 = sstart[n+1];
        for (int j = b; j < e2; j++) acc += sh[ssrt[j]*H + c];
        mg[(size_t)n*H + c] = acc * srdeg[n];
    }
}

// ================= tf32 mma.sync helper (verified layout) =================
__device__ __forceinline__ void mma_tf32(float* d, const uint32_t* a,
                                         uint32_t b0, uint32_t b1) {
    asm volatile(
        "mma.sync.aligned.m16n8k8.row.col.f32.tf32.tf32.f32 "
        "{%0,%1,%2,%3}, {%4,%5,%6,%7}, {%8,%9}, {%0,%1,%2,%3};\n"
        : "+f"(d[0]), "+f"(d[1]), "+f"(d[2]), "+f"(d[3])
        : "r"(a[0]), "r"(a[1]), "r"(a[2]), "r"(a[3]), "r"(b0), "r"(b1));
}

#define WPITCH 132
#define TPITCH 17
#define WP2    132
#define AP2    36
#define STAGEF (32*WP2 + 128*AP2)       // floats per pipeline stage = 8832
#define PIPE_FLOATS (3*STAGEF)          // 26496 floats = 105984 B

// ================= K3a: 3-stage pipelined tensor-core GEMM (256 thr, tile 32x64) =================
template<int RELU, int POOLED>
__global__ __launch_bounds__(256, 2)
void k_gemm_pipe(const float* __restrict__ Wl, const float* __restrict__ Wr,
                 const float* __restrict__ bl,
                 const float* __restrict__ bng, const float* __restrict__ bnb,
                 const float* __restrict__ bnm, const float* __restrict__ bnv)
{
    extern __shared__ float smem[];
    __shared__ float sscale[128], sshift[128];

    const int tid  = threadIdx.x;
    const int row0 = blockIdx.x * 128;
    const float* Am = POOLED ? g_pm : g_mean;
    float*       Ah = POOLED ? g_x2 : g_h;

    if (tid < 128) {
        float sc = bng[tid] * rsqrtf(bnv[tid] + 1e-5f);
        sscale[tid] = sc;
        sshift[tid] = bnb[tid] + sc * (bl[tid] - bnm[tid]);
    }

    const int lane = tid & 31, warp = tid >> 5;
    const int gid = lane >> 2, tig = lane & 3;
    const int wr0 = (warp & 3) * 32;
    const int wc0 = (warp >> 2) * 64;
    float d[2][8][4] = {};

    auto issue = [&](int ch, float* stage) {
        float* sW = stage;
        float* sA = stage + 32*WP2;
        #pragma unroll
        for (int v = 0; v < 4; v++) {
            int i  = tid + v*256;              // 0..1023
            int r  = i >> 3, c4 = (i & 7) * 4;
            int gk = ch*32 + c4;
            int grow = row0 + r;
            const float* ap;
            if (gk < 128) {
                int mrow = POOLED ? (grow / 7) : grow;
                ap = Am + (size_t)mrow*128 + gk;
            } else {
                ap = Ah + (size_t)grow*128 + (gk - 128);
            }
            uint32_t dst = (uint32_t)__cvta_generic_to_shared(&sA[r*AP2 + c4]);
            CP_ASYNC16(dst, ap);
        }
        #pragma unroll
        for (int v = 0; v < 4; v++) {
            int i  = tid + v*256;
            int r  = i >> 5, c4 = (i & 31) * 4;
            int gk = ch*32 + r;
            const float* wp = (gk < 128) ? (Wl + (size_t)gk*128 + c4)
                                         : (Wr + (size_t)(gk - 128)*128 + c4);
            uint32_t dst = (uint32_t)__cvta_generic_to_shared(&sW[r*WP2 + c4]);
            CP_ASYNC16(dst, wp);
        }
        CP_COMMIT();
    };

    issue(0, smem);
    issue(1, smem + STAGEF);
    #pragma unroll
    for (int ch = 0; ch < 8; ch++) {
        if (ch < 7) { CP_WAIT(1); } else { CP_WAIT(0); }
        __syncthreads();                // chunk ch visible; all warps past MMA(ch-1)
        if (ch < 6) issue(ch + 2, smem + ((ch + 2) % 3) * STAGEF);
        const float* stage = smem + (ch % 3) * STAGEF;
        const float* sW = stage;
        const float* sA = stage + 32*WP2;
        #pragma unroll
        for (int ks = 0; ks < 4; ks++) {
            const int kk = ks * 8;
            uint32_t a[2][4];
            #pragma unroll
            for (int mi = 0; mi < 2; mi++) {
                const float* ap = sA + (wr0 + mi*16 + gid)*AP2 + kk + tig;
                a[mi][0] = __float_as_uint(ap[0]);
                a[mi][1] = __float_as_uint(ap[8*AP2]);
                a[mi][2] = __float_as_uint(ap[4]);
                a[mi][3] = __float_as_uint(ap[8*AP2 + 4]);
            }
            const float* bp = sW + (kk + tig)*WP2 + wc0 + gid;
            #pragma unroll
            for (int nj = 0; nj < 8; nj++) {
                uint32_t b0 = __float_as_uint(bp[nj*8]);
                uint32_t b1 = __float_as_uint(bp[nj*8 + 4*WP2]);
                mma_tf32(d[0][nj], a[0], b0, b1);
                mma_tf32(d[1][nj], a[1], b0, b1);
            }
        }
    }

    #pragma unroll
    for (int mi = 0; mi < 2; mi++)
        #pragma unroll
        for (int half = 0; half < 2; half++) {
            const int row = wr0 + mi*16 + gid + half*8;
            float* orow = Ah + (size_t)(row0 + row) * 128;
            #pragma unroll
            for (int nj = 0; nj < 8; nj++) {
                const int col = wc0 + nj*8 + tig*2;
                float2 res = *(float2*)(orow + col);
                float v0 = d[mi][nj][half*2 + 0] * sscale[col]     + sshift[col];
                float v1 = d[mi][nj][half*2 + 1] * sscale[col + 1] + sshift[col + 1];
                if (RELU) { v0 = fmaxf(v0, 0.f); v1 = fmaxf(v1, 0.f); }
                *(float2*)(orow + col) = make_float2(v0 + res.x, v1 + res.y);
            }
        }
}

// ================= K3b: 3-stage pipelined GEMM + fused T epilogue (li=1) =================
// sHf (128 x WPITCH = 67.6KB) overlays the dead 106KB ring after the main loop.
__global__ __launch_bounds__(256, 2)
void k_gemm_pipeT(const float* __restrict__ Wl, const float* __restrict__ Wr,
                  const float* __restrict__ bl,
                  const float* __restrict__ bng, const float* __restrict__ bnb,
                  const float* __restrict__ bnm, const float* __restrict__ bnv,
                  const float* __restrict__ aWl, const float* __restrict__ aWr)
{
    extern __shared__ float smem[];
    float* sHf = smem;                         // overlay after main loop
    __shared__ float sscale[128], sshift[128];
    __shared__ float sW2[128*TPITCH];

    const int tid  = threadIdx.x;
    const int row0 = blockIdx.x * 128;

    if (tid < 128) {
        float sc = bng[tid] * rsqrtf(bnv[tid] + 1e-5f);
        sscale[tid] = sc;
        sshift[tid] = bnb[tid] + sc * (bl[tid] - bnm[tid]);
    }
    for (int i = tid; i < 128*16; i += 256) {
        int k = i >> 4, c = i & 15;
        float v = 0.f;
        if (c < 7)       v = aWl[k*NCL + c];
        else if (c < 14) v = aWr[k*NCL + (c - 7)];
        sW2[k*TPITCH + c] = v;
    }

    const int lane = tid & 31, warp = tid >> 5;
    const int gid = lane >> 2, tig = lane & 3;
    const int wr0 = (warp & 3) * 32;
    const int wc0 = (warp >> 2) * 64;
    float d[2][8][4] = {};

    auto issue = [&](int ch, float* stage) {
        float* sW = stage;
        float* sA = stage + 32*WP2;
        #pragma unroll
        for (int v = 0; v < 4; v++) {
            int i  = tid + v*256;
            int r  = i >> 3, c4 = (i & 7) * 4;
            int gk = ch*32 + c4;
            int grow = row0 + r;
            const float* ap = (gk < 128) ? (g_mean + (size_t)grow*128 + gk)
                                         : (g_h    + (size_t)grow*128 + (gk - 128));
            uint32_t dst = (uint32_t)__cvta_generic_to_shared(&sA[r*AP2 + c4]);
            CP_ASYNC16(dst, ap);
        }
        #pragma unroll
        for (int v = 0; v < 4; v++) {
            int i  = tid + v*256;
            int r  = i >> 5, c4 = (i & 31) * 4;
            int gk = ch*32 + r;
            const float* wp = (gk < 128) ? (Wl + (size_t)gk*128 + c4)
                                         : (Wr + (size_t)(gk - 128)*128 + c4);
            uint32_t dst = (uint32_t)__cvta_generic_to_shared(&sW[r*WP2 + c4]);
            CP_ASYNC16(dst, wp);
        }
        CP_COMMIT();
    };

    issue(0, smem);
    issue(1, smem + STAGEF);
    #pragma unroll
    for (int ch = 0; ch < 8; ch++) {
        if (ch < 7) { CP_WAIT(1); } else { CP_WAIT(0); }
        __syncthreads();
        if (ch < 6) issue(ch + 2, smem + ((ch + 2) % 3) * STAGEF);
        const float* stage = smem + (ch % 3) * STAGEF;
        const float* sW = stage;
        const float* sA = stage + 32*WP2;
        #pragma unroll
        for (int ks = 0; ks < 4; ks++) {
            const int kk = ks * 8;
            uint32_t a[2][4];
            #pragma unroll
            for (int mi = 0; mi < 2; mi++) {
                const float* ap = sA + (wr0 + mi*16 + gid)*AP2 + kk + tig;
                a[mi][0] = __float_as_uint(ap[0]);
                a[mi][1] = __float_as_uint(ap[8*AP2]);
                a[mi][2] = __float_as_uint(ap[4]);
                a[mi][3] = __float_as_uint(ap[8*AP2 + 4]);
            }
            const float* bp = sW + (kk + tig)*WP2 + wc0 + gid;
            #pragma unroll
            for (int nj = 0; nj < 8; nj++) {
                uint32_t b0 = __float_as_uint(bp[nj*8]);
                uint32_t b1 = __float_as_uint(bp[nj*8 + 4*WP2]);
                mma_tf32(d[0][nj], a[0], b0, b1);
                mma_tf32(d[1][nj], a[1], b0, b1);
            }
        }
    }
    __syncthreads();   // all warps done with ring before sHf overlay writes

    // epilogue: bn + relu + residual; write global AND the sHf overlay
    #pragma unroll
    for (int mi = 0; mi < 2; mi++)
        #pragma unroll
        for (int half = 0; half < 2; half++) {
            const int row = wr0 + mi*16 + gid + half*8;
            float* orow = g_h + (size_t)(row0 + row) * 128;
            #pragma unroll
            for (int nj = 0; nj < 8; nj++) {
                const int col = wc0 + nj*8 + tig*2;
                float2 res = *(float2*)(orow + col);
                float v0 = d[mi][nj][half*2 + 0] * sscale[col]     + sshift[col];
                float v1 = d[mi][nj][half*2 + 1] * sscale[col + 1] + sshift[col + 1];
                v0 = fmaxf(v0, 0.f); v1 = fmaxf(v1, 0.f);
                v0 += res.x; v1 += res.y;
                *(float2*)(orow + col) = make_float2(v0, v1);
                sHf[row*WPITCH + col]     = v0;
                sHf[row*WPITCH + col + 1] = v1;
            }
        }

    __syncthreads();
    // T = h_final(sHf) @ W2(sW2, 128x16); warp w owns rows [w*16, w*16+16)
    float dt[2][4] = {};
    #pragma unroll
    for (int ks = 0; ks < 16; ks++) {
        const int kk = ks * 8;
        uint32_t a[4];
        const float* ap = sHf + (warp*16 + gid)*WPITCH + kk + tig;
        a[0] = __float_as_uint(ap[0]);
        a[1] = __float_as_uint(ap[8*WPITCH]);
        a[2] = __float_as_uint(ap[4]);
        a[3] = __float_as_uint(ap[8*WPITCH + 4]);
        #pragma unroll
        for (int nt = 0; nt < 2; nt++) {
            uint32_t b0 = __float_as_uint(sW2[(kk + tig)*TPITCH     + nt*8 + gid]);
            uint32_t b1 = __float_as_uint(sW2[(kk + tig + 4)*TPITCH + nt*8 + gid]);
            mma_tf32(dt[nt], a, b0, b1);
        }
    }
    #pragma unroll
    for (int nt = 0; nt < 2; nt++)
        #pragma unroll
        for (int half = 0; half < 2; half++) {
            const int row = warp*16 + gid + half*8;
            const int col = nt*8 + tig*2;
            float* trow = g_t + (size_t)(row0 + row) * 14;
            if (col < 14)     trow[col]     = dt[nt][half*2 + 0];
            if (col + 1 < 14) trow[col + 1] = dt[nt][half*2 + 1];
        }
}

// ================= K4: per-graph logits-agg + softmax + pooling + losses + pm =================
__global__ void k_pool(const int* __restrict__ ei, const float* __restrict__ abl) {
    __shared__ float sh[NPG * H];
    __shared__ float t1[NPG*NCL], t2[NPG*NCL], ssl[NPG*NCL], sd[NPG*NCL];
    __shared__ float adj[NPG * NPG];
    __shared__ int   se[EPG], de[EPG], degi[NPG];
    __shared__ float red[128], red2[128];
    const int g = blockIdx.x, tid = threadIdx.x;  // 128
    const float* hg = g_h + (size_t)g * NPG * H;
    for (int i = tid; i < NPG * H; i += 128) sh[i] = hg[i];
    for (int i = tid; i < NPG * 14; i += 128) {
        int n = i / 14, c = i - n*14;
        float v = g_t[(size_t)g*NPG*14 + i];
        if (c < 7) t1[n*7 + c] = v; else t2[n*7 + (c-7)] = v;
    }
    for (int i = tid; i < NPG * NPG; i += 128) adj[i] = 0.f;
    for (int i = tid; i < NPG * NCL; i += 128) ssl[i] = 0.f;
    if (tid < NPG) degi[tid] = 0;
    if (tid < EPG) {
        se[tid] = ei[(size_t)g*EPG + tid]                 - g*NPG;
        de[tid] = ei[(size_t)NEDGE + (size_t)g*EPG + tid] - g*NPG;
    }
    __syncthreads();
    if (tid < EPG) {
        atomicAdd(&degi[de[tid]], 1);
        atomicAdd(&adj[se[tid]*NPG + de[tid]], 1.f);
        #pragma unroll
        for (int c = 0; c < NCL; c++)
            atomicAdd(&ssl[de[tid]*NCL + c], t1[se[tid]*NCL + c]);
    }
    __syncthreads();
    for (int i = tid; i < NPG * NCL; i += 128) {
        int n = i / NCL;
        ssl[i] = ssl[i] / fmaxf((float)degi[n], 1.f) + t2[i] + abl[i - n*NCL];
    }
    __syncthreads();
    float ent_local = 0.f;
    if (tid < NPG) {
        float v[NCL], mx = -1e30f;
        #pragma unroll
        for (int c = 0; c < NCL; c++) { v[c] = ssl[tid*NCL + c]; mx = fmaxf(mx, v[c]); }
        float s = 0.f;
        #pragma unroll
        for (int c = 0; c < NCL; c++) { v[c] = expf(v[c] - mx); s += v[c]; }
        float inv = 1.f / s;
        #pragma unroll
        for (int c = 0; c < NCL; c++) {
            float p = v[c] * inv;
            sd[tid*NCL + c] = p;
            ent_local += -p * logf(p + 1e-15f);
        }
    }
    __syncthreads();
    float* x2g = g_x2 + (size_t)g * NCL * H;
    float pmsum = 0.f;
    #pragma unroll
    for (int c = 0; c < NCL; c++) {
        float a = 0.f;
        #pragma unroll
        for (int n = 0; n < NPG; n++) a += sd[n*NCL + c] * sh[n*128 + tid];
        x2g[c*128 + tid] = a;
        pmsum += a;
    }
    g_pm[(size_t)g*128 + tid] = pmsum * (1.f / 7.f);
    float link_local = 0.f;
    for (int p = tid; p < NPG * NPG; p += 128) {
        int n = p / NPG, m = p - NPG*n;
        float ss = 0.f;
        #pragma unroll
        for (int c = 0; c < NCL; c++) ss += sd[n*NCL + c] * sd[m*NCL + c];
        float dd = adj[p] - ss;
        link_local += dd * dd;
    }
    red[tid] = link_local; red2[tid] = ent_local;
    __syncthreads();
    for (int s = 64; s > 0; s >>= 1) {
        if (tid < s) { red[tid] += red[tid + s]; red2[tid] += red2[tid + s]; }
        __syncthreads();
    }
    if (tid == 0) { g_linkpart[g] = red[0]; g_entpart[g] = red2[0]; }
}

// ================= K5: per-graph mean of clusters (for li=3) =================
__global__ void k_pmean() {
    int idx = blockIdx.x * 256 + threadIdx.x;
    int g = idx >> 7, col = idx & 127;
    const float* xg = g_x2 + (size_t)g * NCL * H + col;
    float a = 0.f;
    #pragma unroll
    for (int c = 0; c < NCL; c++) a += xg[c * 128];
    g_pm[idx] = a * (1.f / 7.f);
}

// ================= K6: readout =================
__global__ void k_readout(const float* __restrict__ linW, const float* __restrict__ linb,
                          float* __restrict__ out) {
    const int g = blockIdx.x, tid = threadIdx.x;  // 128
    const float* xg = g_x2 + (size_t)g * NCL * H;
    float v = 0.f;
    #pragma unroll
    for (int c = 0; c < NCL; c++) v += xg[c * 128 + tid];
    v *= (1.f / 7.f);
    __shared__ float red[128];
    red[tid] = v * linW[tid];
    __syncthreads();
    for (int s = 64; s > 0; s >>= 1) {
        if (tid < s) red[tid] += red[tid + s];
        __syncthreads();
    }
    if (tid == 0) out[g] = 1.f / (1.f + expf(-(red[0] + linb[0])));
}

// ================= K7: deterministic loss reduction =================
__global__ void k_reduce(float* __restrict__ out) {
    __shared__ float s1[1024], s2[1024];
    const int tid = threadIdx.x;
    float a = 0.f, b = 0.f;
    for (int i = tid; i < NB; i += 1024) { a += g_linkpart[i]; b += g_entpart[i]; }
    s1[tid] = a; s2[tid] = b;
    __syncthreads();
    for (int s = 512; s > 0; s >>= 1) {
        if (tid < s) { s1[tid] += s1[tid + s]; s2[tid] += s2[tid + s]; }
        __syncthreads();
    }
    if (tid == 0) {
        out[NB]     = sqrtf(s1[0]) / 11075584.f;   // nb * 26 * 26
        out[NB + 1] = s2[0] / (float)NTOT;
    }
}

extern "C" void kernel_launch(void* const* d_in, const int* in_sizes, int n_in,
                              void* d_out, int out_size) {
    (void)in_sizes; (void)n_in; (void)out_size;
    const int*   x    = (const int*)  d_in[0];
    const int*   ei   = (const int*)  d_in[1];
    const float* emb  = (const float*)d_in[3];
    const float* cWl  = (const float*)d_in[4];
    const float* cbl  = (const float*)d_in[5];
    const float* cWr  = (const float*)d_in[6];
    const float* bng  = (const float*)d_in[7];
    const float* bnb  = (const float*)d_in[8];
    const float* bnm  = (const float*)d_in[9];
    const float* bnv  = (const float*)d_in[10];
    const float* aWl  = (const float*)d_in[11];
    const float* abl  = (const float*)d_in[12];
    const float* aWr  = (const float*)d_in[13];
    const float* linW = (const float*)d_in[14];
    const float* linb = (const float*)d_in[15];
    float* out = (float*)d_out;

    const int pipe_smem = PIPE_FLOATS * 4;   // 105984
    cudaFuncSetAttribute(k_gemm_pipe<1,0>, cudaFuncAttributeMaxDynamicSharedMemorySize, pipe_smem);
    cudaFuncSetAttribute(k_gemm_pipe<0,1>, cudaFuncAttributeMaxDynamicSharedMemorySize, pipe_smem);
    cudaFuncSetAttribute(k_gemm_pipeT, cudaFuncAttributeMaxDynamicSharedMemorySize, pipe_smem);

    // layer 0 (encoder fused with aggregation)
    k_encagg<<<NB, 128>>>(x, emb, ei);
    k_gemm_pipe<1,0><<<NTOT / 128, 256, pipe_smem>>>(
        cWl, cWr, cbl, bng, bnb, bnm, bnv);
    // layer 1 (+ fused T = h@[aWl|aWr])
    k_agg2<<<NB, 128>>>(ei);
    k_gemm_pipeT<<<NTOT / 128, 256, pipe_smem>>>(
        cWl + 16384, cWr + 16384, cbl + 128,
        bng + 128, bnb + 128, bnm + 128, bnv + 128, aWl, aWr);

    k_pool<<<NB, 128>>>(ei, abl);     // also writes g_pm (first pmean fused)

    // pooled layer 2
    k_gemm_pipe<0,1><<<NB * NCL / 128, 256, pipe_smem>>>(
        cWl + 2*16384, cWr + 2*16384, cbl + 2*128,
        bng + 2*128, bnb + 2*128, bnm + 2*128, bnv + 2*128);
    // pooled layer 3
    k_pmean<<<NB * 128 / 256, 256>>>();
    k_gemm_pipe<0,1><<<NB * NCL / 128, 256, pipe_smem>>>(
        cWl + 3*16384, cWr + 3*16384, cbl + 3*128,
        bng + 3*128, bnb + 3*128, bnm + 3*128, bnv + 3*128);

    k_readout<<<NB, 128>>>(linW, linb, out);
    k_reduce<<<1, 1024>>>(out);
}

// round 14
// speedup vs baseline: 1.1164x; 1.0467x over previous
#include <cuda_runtime.h>
#include <math.h>
#include <stdint.h>

#define H     128
#define NB    16384
#define NPG   26
#define EPG   52
#define NCL   7
#define NTOT  (NB*NPG)      // 425984
#define NEDGE (NB*EPG)      // 851968

// ------------- scratch: device globals (no runtime allocation) -------------
__device__ float g_h[NTOT*H];
__device__ float g_mean[NTOT*H];
__device__ float g_t[NTOT*14];
__device__ float g_x2[NB*NCL*H];
__device__ float g_pm[NB*H];
__device__ float g_linkpart[NB];
__device__ float g_entpart[NB];
__device__ float g_wp[4*256*128];    // permuted [Wl;Wr] per layer (see k_wt)

// ---- cp.async helpers ----
#define CP_ASYNC16(dst, src) \
    asm volatile("cp.async.cg.shared.global [%0], [%1], 16;\n" :: "r"(dst), "l"(src))
#define CP_COMMIT() asm volatile("cp.async.commit_group;\n" ::: "memory")
#define CP_WAIT(n)  asm volatile("cp.async.wait_group %0;\n" :: "n"(n) : "memory")

// ================= K0: one-time weight permute =================
// Wcomb[k][n] (k<128: Wl, else Wr) -> g_wp[li][((kb*4+p)*128 + n)*2 + h]
// where kb=k>>3, h=(k>>2)&1, p=k&3. Thread fragment pair (k, k+4) becomes
// an adjacent float2 -> LDS64 b-fragment loads in the GEMM.
__global__ void k_wt(const float* __restrict__ cWl, const float* __restrict__ cWr) {
    int idx = blockIdx.x * 256 + threadIdx.x;      // 4*32768 total
    int li = idx >> 15, rem = idx & 32767;
    int k = rem >> 7, n = rem & 127;
    float v = (k < 128) ? cWl[li*16384 + k*128 + n]
                        : cWr[li*16384 + (k-128)*128 + n];
    int kb = k >> 3, h = (k >> 2) & 1, p = k & 3;
    g_wp[li*32768 + (((kb*4 + p)*128) + n)*2 + h] = v;
}

// ================= K1: fused atom encoder + layer-0 neighbor mean =================
__global__ __launch_bounds__(128)
void k_encagg(const int* __restrict__ x, const float* __restrict__ emb,
              const int* __restrict__ ei) {
    __shared__ float sh[NPG * H];
    __shared__ int   sx[NPG * 9];
    __shared__ int   se[EPG], sde[EPG], sdeg[NPG], sstart[NPG+1], soffs[NPG], ssrt[EPG];
    __shared__ float srdeg[NPG];
    const int g = blockIdx.x, tid = threadIdx.x;
    for (int i = tid; i < NPG*9; i += 128) sx[i] = x[(size_t)g*NPG*9 + i];
    if (tid < NPG) sdeg[tid] = 0;
    if (tid < EPG) {
        se[tid]  = ei[(size_t)g*EPG + tid]                 - g*NPG;
        sde[tid] = ei[(size_t)NEDGE + (size_t)g*EPG + tid] - g*NPG;
    }
    __syncthreads();
    if (tid < EPG) atomicAdd(&sdeg[sde[tid]], 1);
    __syncthreads();
    if (tid == 0) {
        int acc = 0;
        #pragma unroll
        for (int n = 0; n < NPG; n++) { sstart[n] = acc; acc += sdeg[n]; }
        sstart[NPG] = acc;
    }
    if (tid < NPG) srdeg[tid] = 1.f / fmaxf((float)sdeg[tid], 1.f);
    __syncthreads();
    if (tid < NPG) soffs[tid] = sstart[tid];
    __syncthreads();
    if (tid < EPG) {
        int pos = atomicAdd(&soffs[sde[tid]], 1);
        ssrt[pos] = se[tid];
    }
    float* hg = g_h + (size_t)g * NPG * H;
    for (int n = 0; n < NPG; n++) {
        float acc = 0.f;
        #pragma unroll
        for (int f = 0; f < 9; f++) {
            int v = sx[n*9 + f];
            acc += __ldg(&emb[((size_t)f*119 + v)*128 + tid]);
        }
        sh[n*H + tid] = acc;
        hg[(size_t)n*H + tid] = acc;
    }
    __syncthreads();
    float* mg = g_mean + (size_t)g * NPG * H;
    #pragma unroll 2
    for (int n = 0; n < NPG; n++) {
        float acc = 0.f;
        int b = sstart[n], e2 = sstart[n+1];
        for (int j = b; j < e2; j++) acc += sh[ssrt[j]*H + tid];
        mg[(size_t)n*H + tid] = acc * srdeg[n];
    }
}

// ================= K2: neighbor-mean via CSR counting sort =================
__global__ __launch_bounds__(128)
void k_agg2(const int* __restrict__ ei) {
    __shared__ float sh[NPG * H];
    __shared__ int   se[EPG], sde[EPG], sdeg[NPG], sstart[NPG+1], soffs[NPG], ssrt[EPG];
    __shared__ float srdeg[NPG];
    const int g = blockIdx.x, tid = threadIdx.x;
    const float* hg = g_h + (size_t)g * NPG * H;
    for (int i = tid; i < NPG*32; i += 128)
        *(float4*)&sh[i*4] = *(const float4*)(hg + (size_t)i*4);
    if (tid < NPG) sdeg[tid] = 0;
    __syncthreads();
    if (tid < EPG) {
        int s = ei[(size_t)g*EPG + tid]                 - g*NPG;
        int d = ei[(size_t)NEDGE + (size_t)g*EPG + tid] - g*NPG;
        se[tid] = s; sde[tid] = d;
        atomicAdd(&sdeg[d], 1);
    }
    __syncthreads();
    if (tid == 0) {
        int acc = 0;
        #pragma unroll
        for (int n = 0; n < NPG; n++) { sstart[n] = acc; acc += sdeg[n]; }
        sstart[NPG] = acc;
    }
    if (tid < NPG) srdeg[tid] = 1.f / fmaxf((float)sdeg[tid], 1.f);
    __syncthreads();
    if (tid < NPG) soffs[tid] = sstart[tid];
    __syncthreads();
    if (tid < EPG) {
        int pos = atomicAdd(&soffs[sde[tid]], 1);
        ssrt[pos] = se[tid];
    }
    __syncthreads();
    float* mg = g_mean + (size_t)g * NPG * H;
    const int c = tid;
    #pragma unroll 2
    for (int n = 0; n < NPG; n++) {
        float acc = 0.f;
        int b = sstart[n], e2 = sstart[n+1];
        for (int j = b; j < e2; j++) acc += sh[ssrt[j]*H + c];
        mg[(size_t)n*H + c] = acc * srdeg[n];
    }
}

// ================= tf32 mma.sync helper (verified layout) =================
__device__ __forceinline__ void mma_tf32(float* d, const uint32_t* a,
                                         uint32_t b0, uint32_t b1) {
    asm volatile(
        "mma.sync.aligned.m16n8k8.row.col.f32.tf32.tf32.f32 "
        "{%0,%1,%2,%3}, {%4,%5,%6,%7}, {%8,%9}, {%0,%1,%2,%3};\n"
        : "+f"(d[0]), "+f"(d[1]), "+f"(d[2]), "+f"(d[3])
        : "r"(a[0]), "r"(a[1]), "r"(a[2]), "r"(a[3]), "r"(b0), "r"(b1));
}

#define WPITCH 132
#define TPITCH 17
#define BP2    264                      // permuted-W stage pitch (floats/row)
#define AP2    36
#define STAGEF (16*BP2 + 128*AP2)       // 4224 + 4608 = 8832 floats / stage
#define PIPE_FLOATS (3*STAGEF)          // 26496 floats = 105984 B

// ================= K3a: 3-stage pipelined GEMM, permuted-W LDS64 b-frags =================
template<int RELU, int POOLED>
__global__ __launch_bounds__(256, 2)
void k_gemm_pipe(const float* __restrict__ wp,
                 const float* __restrict__ bl,
                 const float* __restrict__ bng, const float* __restrict__ bnb,
                 const float* __restrict__ bnm, const float* __restrict__ bnv)
{
    extern __shared__ float smem[];
    __shared__ float sscale[128], sshift[128];

    const int tid  = threadIdx.x;
    const int row0 = blockIdx.x * 128;
    const float* Am = POOLED ? g_pm : g_mean;
    float*       Ah = POOLED ? g_x2 : g_h;

    if (tid < 128) {
        float sc = bng[tid] * rsqrtf(bnv[tid] + 1e-5f);
        sscale[tid] = sc;
        sshift[tid] = bnb[tid] + sc * (bl[tid] - bnm[tid]);
    }

    const int lane = tid & 31, warp = tid >> 5;
    const int gid = lane >> 2, tig = lane & 3;
    const int wr0 = (warp & 3) * 32;
    const int wc0 = (warp >> 2) * 64;
    float d[2][8][4] = {};

    auto issue = [&](int ch, float* stage) {
        float* sW = stage;                 // 16 x BP2
        float* sA = stage + 16*BP2;        // 128 x AP2
        #pragma unroll
        for (int v = 0; v < 4; v++) {
            int i  = tid + v*256;              // 0..1023
            int r  = i >> 3, c4 = (i & 7) * 4;
            int gk = ch*32 + c4;
            int grow = row0 + r;
            const float* ap;
            if (gk < 128) {
                int mrow = POOLED ? (grow / 7) : grow;
                ap = Am + (size_t)mrow*128 + gk;
            } else {
                ap = Ah + (size_t)grow*128 + (gk - 128);
            }
            uint32_t dst = (uint32_t)__cvta_generic_to_shared(&sA[r*AP2 + c4]);
            CP_ASYNC16(dst, ap);
        }
        #pragma unroll
        for (int v = 0; v < 4; v++) {
            int i  = tid + v*256;              // 0..1023
            int r  = i >> 6, c4 = (i & 63) * 4; // 16 rows x 256 floats
            const float* src = wp + (size_t)(ch*16 + r)*256 + c4;
            uint32_t dst = (uint32_t)__cvta_generic_to_shared(&sW[r*BP2 + c4]);
            CP_ASYNC16(dst, src);
        }
        CP_COMMIT();
    };

    issue(0, smem);
    issue(1, smem + STAGEF);
    #pragma unroll
    for (int ch = 0; ch < 8; ch++) {
        if (ch < 7) { CP_WAIT(1); } else { CP_WAIT(0); }
        __syncthreads();
        if (ch < 6) issue(ch + 2, smem + ((ch + 2) % 3) * STAGEF);
        const float* stage = smem + (ch % 3) * STAGEF;
        const float* sW = stage;
        const float* sA = stage + 16*BP2;
        #pragma unroll
        for (int ks = 0; ks < 4; ks++) {
            const int kk = ks * 8;
            uint32_t a[2][4];
            #pragma unroll
            for (int mi = 0; mi < 2; mi++) {
                const float* ap = sA + (wr0 + mi*16 + gid)*AP2 + kk + tig;
                a[mi][0] = __float_as_uint(ap[0]);
                a[mi][1] = __float_as_uint(ap[8*AP2]);
                a[mi][2] = __float_as_uint(ap[4]);
                a[mi][3] = __float_as_uint(ap[8*AP2 + 4]);
            }
            const float2* bp = (const float2*)&sW[(ks*4 + tig)*BP2] + (wc0 + gid);
            #pragma unroll
            for (int nj = 0; nj < 8; nj++) {
                float2 bv = bp[nj*8];
                uint32_t b0 = __float_as_uint(bv.x);
                uint32_t b1 = __float_as_uint(bv.y);
                mma_tf32(d[0][nj], a[0], b0, b1);
                mma_tf32(d[1][nj], a[1], b0, b1);
            }
        }
    }

    #pragma unroll
    for (int mi = 0; mi < 2; mi++)
        #pragma unroll
        for (int half = 0; half < 2; half++) {
            const int row = wr0 + mi*16 + gid + half*8;
            float* orow = Ah + (size_t)(row0 + row) * 128;
            #pragma unroll
            for (int nj = 0; nj < 8; nj++) {
                const int col = wc0 + nj*8 + tig*2;
                float2 res = *(float2*)(orow + col);
                float v0 = d[mi][nj][half*2 + 0] * sscale[col]     + sshift[col];
                float v1 = d[mi][nj][half*2 + 1] * sscale[col + 1] + sshift[col + 1];
                if (RELU) { v0 = fmaxf(v0, 0.f); v1 = fmaxf(v1, 0.f); }
                *(float2*)(orow + col) = make_float2(v0 + res.x, v1 + res.y);
            }
        }
}

// ================= K3b: 3-stage pipelined GEMM + fused T epilogue (li=1) =================
__global__ __launch_bounds__(256, 2)
void k_gemm_pipeT(const float* __restrict__ wp,
                  const float* __restrict__ bl,
                  const float* __restrict__ bng, const float* __restrict__ bnb,
                  const float* __restrict__ bnm, const float* __restrict__ bnv,
                  const float* __restrict__ aWl, const float* __restrict__ aWr)
{
    extern __shared__ float smem[];
    float* sHf = smem;                         // overlay after main loop
    __shared__ float sscale[128], sshift[128];
    __shared__ float sW2[128*TPITCH];

    const int tid  = threadIdx.x;
    const int row0 = blockIdx.x * 128;

    if (tid < 128) {
        float sc = bng[tid] * rsqrtf(bnv[tid] + 1e-5f);
        sscale[tid] = sc;
        sshift[tid] = bnb[tid] + sc * (bl[tid] - bnm[tid]);
    }
    for (int i = tid; i < 128*16; i += 256) {
        int k = i >> 4, c = i & 15;
        float v = 0.f;
        if (c < 7)       v = aWl[k*NCL + c];
        else if (c < 14) v = aWr[k*NCL + (c - 7)];
        sW2[k*TPITCH + c] = v;
    }

    const int lane = tid & 31, warp = tid >> 5;
    const int gid = lane >> 2, tig = lane & 3;
    const int wr0 = (warp & 3) * 32;
    const int wc0 = (warp >> 2) * 64;
    float d[2][8][4] = {};

    auto issue = [&](int ch, float* stage) {
        float* sW = stage;
        float* sA = stage + 16*BP2;
        #pragma unroll
        for (int v = 0; v < 4; v++) {
            int i  = tid + v*256;
            int r  = i >> 3, c4 = (i & 7) * 4;
            int gk = ch*32 + c4;
            int grow = row0 + r;
            const float* ap = (gk < 128) ? (g_mean + (size_t)grow*128 + gk)
                                         : (g_h    + (size_t)grow*128 + (gk - 128));
            uint32_t dst = (uint32_t)__cvta_generic_to_shared(&sA[r*AP2 + c4]);
            CP_ASYNC16(dst, ap);
        }
        #pragma unroll
        for (int v = 0; v < 4; v++) {
            int i  = tid + v*256;
            int r  = i >> 6, c4 = (i & 63) * 4;
            const float* src = wp + (size_t)(ch*16 + r)*256 + c4;
            uint32_t dst = (uint32_t)__cvta_generic_to_shared(&sW[r*BP2 + c4]);
            CP_ASYNC16(dst, src);
        }
        CP_COMMIT();
    };

    issue(0, smem);
    issue(1, smem + STAGEF);
    #pragma unroll
    for (int ch = 0; ch < 8; ch++) {
        if (ch < 7) { CP_WAIT(1); } else { CP_WAIT(0); }
        __syncthreads();
        if (ch < 6) issue(ch + 2, smem + ((ch + 2) % 3) * STAGEF);
        const float* stage = smem + (ch % 3) * STAGEF;
        const float* sW = stage;
        const float* sA = stage + 16*BP2;
        #pragma unroll
        for (int ks = 0; ks < 4; ks++) {
            const int kk = ks * 8;
            uint32_t a[2][4];
            #pragma unroll
            for (int mi = 0; mi < 2; mi++) {
                const float* ap = sA + (wr0 + mi*16 + gid)*AP2 + kk + tig;
                a[mi][0] = __float_as_uint(ap[0]);
                a[mi][1] = __float_as_uint(ap[8*AP2]);
                a[mi][2] = __float_as_uint(ap[4]);
                a[mi][3] = __float_as_uint(ap[8*AP2 + 4]);
            }
            const float2* bp = (const float2*)&sW[(ks*4 + tig)*BP2] + (wc0 + gid);
            #pragma unroll
            for (int nj = 0; nj < 8; nj++) {
                float2 bv = bp[nj*8];
                uint32_t b0 = __float_as_uint(bv.x);
                uint32_t b1 = __float_as_uint(bv.y);
                mma_tf32(d[0][nj], a[0], b0, b1);
                mma_tf32(d[1][nj], a[1], b0, b1);
            }
        }
    }
    __syncthreads();   // all warps done with ring before sHf overlay writes

    // epilogue: bn + relu + residual; write global AND the sHf overlay
    #pragma unroll
    for (int mi = 0; mi < 2; mi++)
        #pragma unroll
        for (int half = 0; half < 2; half++) {
            const int row = wr0 + mi*16 + gid + half*8;
            float* orow = g_h + (size_t)(row0 + row) * 128;
            #pragma unroll
            for (int nj = 0; nj < 8; nj++) {
                const int col = wc0 + nj*8 + tig*2;
                float2 res = *(float2*)(orow + col);
                float v0 = d[mi][nj][half*2 + 0] * sscale[col]     + sshift[col];
                float v1 = d[mi][nj][half*2 + 1] * sscale[col + 1] + sshift[col + 1];
                v0 = fmaxf(v0, 0.f); v1 = fmaxf(v1, 0.f);
                v0 += res.x; v1 += res.y;
                *(float2*)(orow + col) = make_float2(v0, v1);
                sHf[row*WPITCH + col]     = v0;
                sHf[row*WPITCH + col + 1] = v1;
            }
        }

    __syncthreads();
    // T = h_final(sHf) @ W2(sW2, 128x16); warp w owns rows [w*16, w*16+16)
    float dt[2][4] = {};
    #pragma unroll
    for (int ks = 0; ks < 16; ks++) {
        const int kk = ks * 8;
        uint32_t a[4];
        const float* ap = sHf + (warp*16 + gid)*WPITCH + kk + tig;
        a[0] = __float_as_uint(ap[0]);
        a[1] = __float_as_uint(ap[8*WPITCH]);
        a[2] = __float_as_uint(ap[4]);
        a[3] = __float_as_uint(ap[8*WPITCH + 4]);
        #pragma unroll
        for (int nt = 0; nt < 2; nt++) {
            uint32_t b0 = __float_as_uint(sW2[(kk + tig)*TPITCH     + nt*8 + gid]);
            uint32_t b1 = __float_as_uint(sW2[(kk + tig + 4)*TPITCH + nt*8 + gid]);
            mma_tf32(dt[nt], a, b0, b1);
        }
    }
    #pragma unroll
    for (int nt = 0; nt < 2; nt++)
        #pragma unroll
        for (int half = 0; half < 2; half++) {
            const int row = warp*16 + gid + half*8;
            const int col = nt*8 + tig*2;
            float* trow = g_t + (size_t)(row0 + row) * 14;
            if (col < 14)     trow[col]     = dt[nt][half*2 + 0];
            if (col + 1 < 14) trow[col + 1] = dt[nt][half*2 + 1];
        }
}

// ================= K4: per-graph logits-agg + softmax + pooling + losses + pm =================
__global__ void k_pool(const int* __restrict__ ei, const float* __restrict__ abl) {
    __shared__ float sh[NPG * H];
    __shared__ float t1[NPG*NCL], t2[NPG*NCL], ssl[NPG*NCL], sd[NPG*NCL];
    __shared__ float adj[NPG * NPG];
    __shared__ int   se[EPG], de[EPG], degi[NPG];
    __shared__ float red[128], red2[128];
    const int g = blockIdx.x, tid = threadIdx.x;
    const float* hg = g_h + (size_t)g * NPG * H;
    for (int i = tid; i < NPG * H; i += 128) sh[i] = hg[i];
    for (int i = tid; i < NPG * 14; i += 128) {
        int n = i / 14, c = i - n*14;
        float v = g_t[(size_t)g*NPG*14 + i];
        if (c < 7) t1[n*7 + c] = v; else t2[n*7 + (c-7)] = v;
    }
    for (int i = tid; i < NPG * NPG; i += 128) adj[i] = 0.f;
    for (int i = tid; i < NPG * NCL; i += 128) ssl[i] = 0.f;
    if (tid < NPG) degi[tid] = 0;
    if (tid < EPG) {
        se[tid] = ei[(size_t)g*EPG + tid]                 - g*NPG;
        de[tid] = ei[(size_t)NEDGE + (size_t)g*EPG + tid] - g*NPG;
    }
    __syncthreads();
    if (tid < EPG) {
        atomicAdd(&degi[de[tid]], 1);
        atomicAdd(&adj[se[tid]*NPG + de[tid]], 1.f);
        #pragma unroll
        for (int c = 0; c < NCL; c++)
            atomicAdd(&ssl[de[tid]*NCL + c], t1[se[tid]*NCL + c]);
    }
    __syncthreads();
    for (int i = tid; i < NPG * NCL; i += 128) {
        int n = i / NCL;
        ssl[i] = ssl[i] / fmaxf((float)degi[n], 1.f) + t2[i] + abl[i - n*NCL];
    }
    __syncthreads();
    float ent_local = 0.f;
    if (tid < NPG) {
        float v[NCL], mx = -1e30f;
        #pragma unroll
        for (int c = 0; c < NCL; c++) { v[c] = ssl[tid*NCL + c]; mx = fmaxf(mx, v[c]); }
        float s = 0.f;
        #pragma unroll
        for (int c = 0; c < NCL; c++) { v[c] = expf(v[c] - mx); s += v[c]; }
        float inv = 1.f / s;
        #pragma unroll
        for (int c = 0; c < NCL; c++) {
            float p = v[c] * inv;
            sd[tid*NCL + c] = p;
            ent_local += -p * logf(p + 1e-15f);
        }
    }
    __syncthreads();
    float* x2g = g_x2 + (size_t)g * NCL * H;
    float pmsum = 0.f;
    #pragma unroll
    for (int c = 0; c < NCL; c++) {
        float a = 0.f;
        #pragma unroll
        for (int n = 0; n < NPG; n++) a += sd[n*NCL + c] * sh[n*128 + tid];
        x2g[c*128 + tid] = a;
        pmsum += a;
    }
    g_pm[(size_t)g*128 + tid] = pmsum * (1.f / 7.f);
    float link_local = 0.f;
    for (int p = tid; p < NPG * NPG; p += 128) {
        int n = p / NPG, m = p - NPG*n;
        float ss = 0.f;
        #pragma unroll
        for (int c = 0; c < NCL; c++) ss += sd[n*NCL + c] * sd[m*NCL + c];
        float dd = adj[p] - ss;
        link_local += dd * dd;
    }
    red[tid] = link_local; red2[tid] = ent_local;
    __syncthreads();
    for (int s = 64; s > 0; s >>= 1) {
        if (tid < s) { red[tid] += red[tid + s]; red2[tid] += red2[tid + s]; }
        __syncthreads();
    }
    if (tid == 0) { g_linkpart[g] = red[0]; g_entpart[g] = red2[0]; }
}

// ================= K5: per-graph mean of clusters (for li=3) =================
__global__ void k_pmean() {
    int idx = blockIdx.x * 256 + threadIdx.x;
    int g = idx >> 7, col = idx & 127;
    const float* xg = g_x2 + (size_t)g * NCL * H + col;
    float a = 0.f;
    #pragma unroll
    for (int c = 0; c < NCL; c++) a += xg[c * 128];
    g_pm[idx] = a * (1.f / 7.f);
}

// ================= K6: readout =================
__global__ void k_readout(const float* __restrict__ linW, const float* __restrict__ linb,
                          float* __restrict__ out) {
    const int g = blockIdx.x, tid = threadIdx.x;
    const float* xg = g_x2 + (size_t)g * NCL * H;
    float v = 0.f;
    #pragma unroll
    for (int c = 0; c < NCL; c++) v += xg[c * 128 + tid];
    v *= (1.f / 7.f);
    __shared__ float red[128];
    red[tid] = v * linW[tid];
    __syncthreads();
    for (int s = 64; s > 0; s >>= 1) {
        if (tid < s) red[tid] += red[tid + s];
        __syncthreads();
    }
    if (tid == 0) out[g] = 1.f / (1.f + expf(-(red[0] + linb[0])));
}

// ================= K7: deterministic loss reduction =================
__global__ void k_reduce(float* __restrict__ out) {
    __shared__ float s1[1024], s2[1024];
    const int tid = threadIdx.x;
    float a = 0.f, b = 0.f;
    for (int i = tid; i < NB; i += 1024) { a += g_linkpart[i]; b += g_entpart[i]; }
    s1[tid] = a; s2[tid] = b;
    __syncthreads();
    for (int s = 512; s > 0; s >>= 1) {
        if (tid < s) { s1[tid] += s1[tid + s]; s2[tid] += s2[tid + s]; }
        __syncthreads();
    }
    if (tid == 0) {
        out[NB]     = sqrtf(s1[0]) / 11075584.f;
        out[NB + 1] = s2[0] / (float)NTOT;
    }
}

extern "C" void kernel_launch(void* const* d_in, const int* in_sizes, int n_in,
                              void* d_out, int out_size) {
    (void)in_sizes; (void)n_in; (void)out_size;
    const int*   x    = (const int*)  d_in[0];
    const int*   ei   = (const int*)  d_in[1];
    const float* emb  = (const float*)d_in[3];
    const float* cWl  = (const float*)d_in[4];
    const float* cbl  = (const float*)d_in[5];
    const float* cWr  = (const float*)d_in[6];
    const float* bng  = (const float*)d_in[7];
    const float* bnb  = (const float*)d_in[8];
    const float* bnm  = (const float*)d_in[9];
    const float* bnv  = (const float*)d_in[10];
    const float* aWl  = (const float*)d_in[11];
    const float* abl  = (const float*)d_in[12];
    const float* aWr  = (const float*)d_in[13];
    const float* linW = (const float*)d_in[14];
    const float* linb = (const float*)d_in[15];
    float* out = (float*)d_out;

    float* wp;
    cudaGetSymbolAddress((void**)&wp, g_wp);

    const int pipe_smem = PIPE_FLOATS * 4;   // 105984
    cudaFuncSetAttribute(k_gemm_pipe<1,0>, cudaFuncAttributeMaxDynamicSharedMemorySize, pipe_smem);
    cudaFuncSetAttribute(k_gemm_pipe<0,1>, cudaFuncAttributeMaxDynamicSharedMemorySize, pipe_smem);
    cudaFuncSetAttribute(k_gemm_pipeT, cudaFuncAttributeMaxDynamicSharedMemorySize, pipe_smem);

    k_wt<<<4*32768/256, 256>>>(cWl, cWr);

    // layer 0 (encoder fused with aggregation)
    k_encagg<<<NB, 128>>>(x, emb, ei);
    k_gemm_pipe<1,0><<<NTOT / 128, 256, pipe_smem>>>(
        wp, cbl, bng, bnb, bnm, bnv);
    // layer 1 (+ fused T = h@[aWl|aWr])
    k_agg2<<<NB, 128>>>(ei);
    k_gemm_pipeT<<<NTOT / 128, 256, pipe_smem>>>(
        wp + 32768, cbl + 128,
        bng + 128, bnb + 128, bnm + 128, bnv + 128, aWl, aWr);

    k_pool<<<NB, 128>>>(ei, abl);     // also writes g_pm (first pmean fused)

    // pooled layer 2
    k_gemm_pipe<0,1><<<NB * NCL / 128, 256, pipe_smem>>>(
        wp + 2*32768, cbl + 2*128,
        bng + 2*128, bnb + 2*128, bnm + 2*128, bnv + 2*128);
    // pooled layer 3
    k_pmean<<<NB * 128 / 256, 256>>>();
    k_gemm_pipe<0,1><<<NB * NCL / 128, 256, pipe_smem>>>(
        wp + 3*32768, cbl + 3*128,
        bng + 3*128, bnb + 3*128, bnm + 3*128, bnv + 3*128);

    k_readout<<<NB, 128>>>(linW, linb, out);
    k_reduce<<<1, 1024>>>(out);
}

// round 15
// speedup vs baseline: 1.1201x; 1.0033x over previous
#include <cuda_runtime.h>
#include <math.h>
#include <stdint.h>

#define H     128
#define NB    16384
#define NPG   26
#define EPG   52
#define NCL   7
#define NTOT  (NB*NPG)      // 425984
#define NEDGE (NB*EPG)      // 851968

// ------------- scratch: device globals (no runtime allocation) -------------
__device__ float g_h[NTOT*H];
__device__ float g_mean[NTOT*H];
__device__ float g_t[NTOT*14];
__device__ float g_x2[NB*NCL*H];
__device__ float g_pm[NB*H];
__device__ float g_linkpart[NB];
__device__ float g_entpart[NB];
__device__ float g_wp[4*256*128];    // permuted [Wl;Wr] per layer (see k_wt)

// ---- cp.async helpers ----
#define CP_ASYNC16(dst, src) \
    asm volatile("cp.async.cg.shared.global [%0], [%1], 16;\n" :: "r"(dst), "l"(src))
#define CP_COMMIT() asm volatile("cp.async.commit_group;\n" ::: "memory")
#define CP_WAIT(n)  asm volatile("cp.async.wait_group %0;\n" :: "n"(n) : "memory")

// ================= K0: one-time weight permute =================
__global__ void k_wt(const float* __restrict__ cWl, const float* __restrict__ cWr) {
    int idx = blockIdx.x * 256 + threadIdx.x;      // 4*32768 total
    int li = idx >> 15, rem = idx & 32767;
    int k = rem >> 7, n = rem & 127;
    float v = (k < 128) ? cWl[li*16384 + k*128 + n]
                        : cWr[li*16384 + (k-128)*128 + n];
    int kb = k >> 3, h = (k >> 2) & 1, p = k & 3;
    g_wp[li*32768 + (((kb*4 + p)*128) + n)*2 + h] = v;
}

// ================= K1: fused atom encoder + layer-0 neighbor mean =================
__global__ __launch_bounds__(128)
void k_encagg(const int* __restrict__ x, const float* __restrict__ emb,
              const int* __restrict__ ei) {
    __shared__ float sh[NPG * H];
    __shared__ int   sx[NPG * 9];
    __shared__ int   se[EPG], sde[EPG], sdeg[NPG], sstart[NPG+1], soffs[NPG], ssrt[EPG];
    __shared__ int   soff2[EPG], swd[EPG];
    __shared__ float srdeg[NPG];
    const int g = blockIdx.x, tid = threadIdx.x;
    for (int i = tid; i < NPG*9; i += 128) sx[i] = x[(size_t)g*NPG*9 + i];
    if (tid < NPG) sdeg[tid] = 0;
    if (tid < EPG) {
        se[tid]  = ei[(size_t)g*EPG + tid]                 - g*NPG;
        sde[tid] = ei[(size_t)NEDGE + (size_t)g*EPG + tid] - g*NPG;
        swd[tid] = -1;
    }
    __syncthreads();
    if (tid < EPG) atomicAdd(&sdeg[sde[tid]], 1);
    __syncthreads();
    if (tid == 0) {
        int acc = 0;
        #pragma unroll
        for (int n = 0; n < NPG; n++) { sstart[n] = acc; acc += sdeg[n]; }
        sstart[NPG] = acc;
    }
    if (tid < NPG) srdeg[tid] = 1.f / fmaxf((float)sdeg[tid], 1.f);
    __syncthreads();
    if (tid < NPG) soffs[tid] = sstart[tid];
    __syncthreads();
    if (tid < EPG) {
        int pos = atomicAdd(&soffs[sde[tid]], 1);
        ssrt[pos] = se[tid];
    }
    if (tid < NPG && sdeg[tid] > 0) swd[sstart[tid+1] - 1] = tid;
    float* hg = g_h + (size_t)g * NPG * H;
    for (int n = 0; n < NPG; n++) {
        float acc = 0.f;
        #pragma unroll
        for (int f = 0; f < 9; f++) {
            int v = sx[n*9 + f];
            acc += __ldg(&emb[((size_t)f*119 + v)*128 + tid]);
        }
        sh[n*H + tid] = acc;
        hg[(size_t)n*H + tid] = acc;
    }
    __syncthreads();
    if (tid < EPG) soff2[tid] = ssrt[tid] * H;
    __syncthreads();
    float* mg = g_mean + (size_t)g * NPG * H;
    const int c = tid;
    float acc = 0.f;
    #pragma unroll 4
    for (int j = 0; j < EPG; j++) {
        acc += sh[soff2[j] + c];
        int w = swd[j];
        if (w >= 0) { mg[(size_t)w*H + c] = acc * srdeg[w]; acc = 0.f; }
    }
    #pragma unroll
    for (int n = 0; n < NPG; n++)
        if (sdeg[n] == 0) mg[(size_t)n*H + c] = 0.f;
}

// ================= K2: neighbor-mean via segmented-scan CSR =================
__global__ __launch_bounds__(128)
void k_agg2(const int* __restrict__ ei) {
    __shared__ float sh[NPG * H];
    __shared__ int   se[EPG], sde[EPG], sdeg[NPG], sstart[NPG+1], soffs[NPG], ssrt[EPG];
    __shared__ int   soff2[EPG], swd[EPG];
    __shared__ float srdeg[NPG];
    const int g = blockIdx.x, tid = threadIdx.x;
    const float* hg = g_h + (size_t)g * NPG * H;
    for (int i = tid; i < NPG*32; i += 128)
        *(float4*)&sh[i*4] = *(const float4*)(hg + (size_t)i*4);
    if (tid < NPG) sdeg[tid] = 0;
    if (tid < EPG) swd[tid] = -1;
    __syncthreads();
    if (tid < EPG) {
        int s = ei[(size_t)g*EPG + tid]                 - g*NPG;
        int d = ei[(size_t)NEDGE + (size_t)g*EPG + tid] - g*NPG;
        se[tid] = s; sde[tid] = d;
        atomicAdd(&sdeg[d], 1);
    }
    __syncthreads();
    if (tid == 0) {
        int acc = 0;
        #pragma unroll
        for (int n = 0; n < NPG; n++) { sstart[n] = acc; acc += sdeg[n]; }
        sstart[NPG] = acc;
    }
    if (tid < NPG) srdeg[tid] = 1.f / fmaxf((float)sdeg[tid], 1.f);
    __syncthreads();
    if (tid < NPG) soffs[tid] = sstart[tid];
    __syncthreads();
    if (tid < EPG) {
        int pos = atomicAdd(&soffs[sde[tid]], 1);
        ssrt[pos] = se[tid];
    }
    if (tid < NPG && sdeg[tid] > 0) swd[sstart[tid+1] - 1] = tid;
    __syncthreads();
    if (tid < EPG) soff2[tid] = ssrt[tid] * H;
    __syncthreads();
    float* mg = g_mean + (size_t)g * NPG * H;
    const int c = tid;
    float acc = 0.f;
    #pragma unroll 4
    for (int j = 0; j < EPG; j++) {
        acc += sh[soff2[j] + c];
        int w = swd[j];
        if (w >= 0) { mg[(size_t)w*H + c] = acc * srdeg[w]; acc = 0.f; }
    }
    #pragma unroll
    for (int n = 0; n < NPG; n++)
        if (sdeg[n] == 0) mg[(size_t)n*H + c] = 0.f;
}

// ================= tf32 mma.sync helper (verified layout) =================
__device__ __forceinline__ void mma_tf32(float* d, const uint32_t* a,
                                         uint32_t b0, uint32_t b1) {
    asm volatile(
        "mma.sync.aligned.m16n8k8.row.col.f32.tf32.tf32.f32 "
        "{%0,%1,%2,%3}, {%4,%5,%6,%7}, {%8,%9}, {%0,%1,%2,%3};\n"
        : "+f"(d[0]), "+f"(d[1]), "+f"(d[2]), "+f"(d[3])
        : "r"(a[0]), "r"(a[1]), "r"(a[2]), "r"(a[3]), "r"(b0), "r"(b1));
}

#define WPITCH 132
#define TPITCH 17
#define BP2    264
#define AP2    36
#define STAGEF (16*BP2 + 128*AP2)       // 8832 floats / stage
#define PIPE_FLOATS (3*STAGEF)          // 105984 B

// ================= K3a: 3-stage pipelined GEMM, permuted-W LDS64 b-frags =================
template<int RELU, int POOLED>
__global__ __launch_bounds__(256, 2)
void k_gemm_pipe(const float* __restrict__ wp,
                 const float* __restrict__ bl,
                 const float* __restrict__ bng, const float* __restrict__ bnb,
                 const float* __restrict__ bnm, const float* __restrict__ bnv)
{
    extern __shared__ float smem[];
    __shared__ float sscale[128], sshift[128];

    const int tid  = threadIdx.x;
    const int row0 = blockIdx.x * 128;
    const float* Am = POOLED ? g_pm : g_mean;
    float*       Ah = POOLED ? g_x2 : g_h;

    if (tid < 128) {
        float sc = bng[tid] * rsqrtf(bnv[tid] + 1e-5f);
        sscale[tid] = sc;
        sshift[tid] = bnb[tid] + sc * (bl[tid] - bnm[tid]);
    }

    const int lane = tid & 31, warp = tid >> 5;
    const int gid = lane >> 2, tig = lane & 3;
    const int wr0 = (warp & 3) * 32;
    const int wc0 = (warp >> 2) * 64;
    float d[2][8][4] = {};

    auto issue = [&](int ch, float* stage) {
        float* sW = stage;
        float* sA = stage + 16*BP2;
        #pragma unroll
        for (int v = 0; v < 4; v++) {
            int i  = tid + v*256;
            int r  = i >> 3, c4 = (i & 7) * 4;
            int gk = ch*32 + c4;
            int grow = row0 + r;
            const float* ap;
            if (gk < 128) {
                int mrow = POOLED ? (grow / 7) : grow;
                ap = Am + (size_t)mrow*128 + gk;
            } else {
                ap = Ah + (size_t)grow*128 + (gk - 128);
            }
            uint32_t dst = (uint32_t)__cvta_generic_to_shared(&sA[r*AP2 + c4]);
            CP_ASYNC16(dst, ap);
        }
        #pragma unroll
        for (int v = 0; v < 4; v++) {
            int i  = tid + v*256;
            int r  = i >> 6, c4 = (i & 63) * 4;
            const float* src = wp + (size_t)(ch*16 + r)*256 + c4;
            uint32_t dst = (uint32_t)__cvta_generic_to_shared(&sW[r*BP2 + c4]);
            CP_ASYNC16(dst, src);
        }
        CP_COMMIT();
    };

    issue(0, smem);
    issue(1, smem + STAGEF);
    #pragma unroll
    for (int ch = 0; ch < 8; ch++) {
        if (ch < 7) { CP_WAIT(1); } else { CP_WAIT(0); }
        __syncthreads();
        if (ch < 6) issue(ch + 2, smem + ((ch + 2) % 3) * STAGEF);
        const float* stage = smem + (ch % 3) * STAGEF;
        const float* sW = stage;
        const float* sA = stage + 16*BP2;
        #pragma unroll
        for (int ks = 0; ks < 4; ks++) {
            const int kk = ks * 8;
            uint32_t a[2][4];
            #pragma unroll
            for (int mi = 0; mi < 2; mi++) {
                const float* ap = sA + (wr0 + mi*16 + gid)*AP2 + kk + tig;
                a[mi][0] = __float_as_uint(ap[0]);
                a[mi][1] = __float_as_uint(ap[8*AP2]);
                a[mi][2] = __float_as_uint(ap[4]);
                a[mi][3] = __float_as_uint(ap[8*AP2 + 4]);
            }
            const float2* bp = (const float2*)&sW[(ks*4 + tig)*BP2] + (wc0 + gid);
            #pragma unroll
            for (int nj = 0; nj < 8; nj++) {
                float2 bv = bp[nj*8];
                uint32_t b0 = __float_as_uint(bv.x);
                uint32_t b1 = __float_as_uint(bv.y);
                mma_tf32(d[0][nj], a[0], b0, b1);
                mma_tf32(d[1][nj], a[1], b0, b1);
            }
        }
    }

    #pragma unroll
    for (int mi = 0; mi < 2; mi++)
        #pragma unroll
        for (int half = 0; half < 2; half++) {
            const int row = wr0 + mi*16 + gid + half*8;
            float* orow = Ah + (size_t)(row0 + row) * 128;
            #pragma unroll
            for (int nj = 0; nj < 8; nj++) {
                const int col = wc0 + nj*8 + tig*2;
                float2 res = *(float2*)(orow + col);
                float v0 = d[mi][nj][half*2 + 0] * sscale[col]     + sshift[col];
                float v1 = d[mi][nj][half*2 + 1] * sscale[col + 1] + sshift[col + 1];
                if (RELU) { v0 = fmaxf(v0, 0.f); v1 = fmaxf(v1, 0.f); }
                *(float2*)(orow + col) = make_float2(v0 + res.x, v1 + res.y);
            }
        }
}

// ================= K3b: 3-stage pipelined GEMM + fused T epilogue (li=1) =================
__global__ __launch_bounds__(256, 2)
void k_gemm_pipeT(const float* __restrict__ wp,
                  const float* __restrict__ bl,
                  const float* __restrict__ bng, const float* __restrict__ bnb,
                  const float* __restrict__ bnm, const float* __restrict__ bnv,
                  const float* __restrict__ aWl, const float* __restrict__ aWr)
{
    extern __shared__ float smem[];
    float* sHf = smem;
    __shared__ float sscale[128], sshift[128];
    __shared__ float sW2[128*TPITCH];

    const int tid  = threadIdx.x;
    const int row0 = blockIdx.x * 128;

    if (tid < 128) {
        float sc = bng[tid] * rsqrtf(bnv[tid] + 1e-5f);
        sscale[tid] = sc;
        sshift[tid] = bnb[tid] + sc * (bl[tid] - bnm[tid]);
    }
    for (int i = tid; i < 128*16; i += 256) {
        int k = i >> 4, c = i & 15;
        float v = 0.f;
        if (c < 7)       v = aWl[k*NCL + c];
        else if (c < 14) v = aWr[k*NCL + (c - 7)];
        sW2[k*TPITCH + c] = v;
    }

    const int lane = tid & 31, warp = tid >> 5;
    const int gid = lane >> 2, tig = lane & 3;
    const int wr0 = (warp & 3) * 32;
    const int wc0 = (warp >> 2) * 64;
    float d[2][8][4] = {};

    auto issue = [&](int ch, float* stage) {
        float* sW = stage;
        float* sA = stage + 16*BP2;
        #pragma unroll
        for (int v = 0; v < 4; v++) {
            int i  = tid + v*256;
            int r  = i >> 3, c4 = (i & 7) * 4;
            int gk = ch*32 + c4;
            int grow = row0 + r;
            const float* ap = (gk < 128) ? (g_mean + (size_t)grow*128 + gk)
                                         : (g_h    + (size_t)grow*128 + (gk - 128));
            uint32_t dst = (uint32_t)__cvta_generic_to_shared(&sA[r*AP2 + c4]);
            CP_ASYNC16(dst, ap);
        }
        #pragma unroll
        for (int v = 0; v < 4; v++) {
            int i  = tid + v*256;
            int r  = i >> 6, c4 = (i & 63) * 4;
            const float* src = wp + (size_t)(ch*16 + r)*256 + c4;
            uint32_t dst = (uint32_t)__cvta_generic_to_shared(&sW[r*BP2 + c4]);
            CP_ASYNC16(dst, src);
        }
        CP_COMMIT();
    };

    issue(0, smem);
    issue(1, smem + STAGEF);
    #pragma unroll
    for (int ch = 0; ch < 8; ch++) {
        if (ch < 7) { CP_WAIT(1); } else { CP_WAIT(0); }
        __syncthreads();
        if (ch < 6) issue(ch + 2, smem + ((ch + 2) % 3) * STAGEF);
        const float* stage = smem + (ch % 3) * STAGEF;
        const float* sW = stage;
        const float* sA = stage + 16*BP2;
        #pragma unroll
        for (int ks = 0; ks < 4; ks++) {
            const int kk = ks * 8;
            uint32_t a[2][4];
            #pragma unroll
            for (int mi = 0; mi < 2; mi++) {
                const float* ap = sA + (wr0 + mi*16 + gid)*AP2 + kk + tig;
                a[mi][0] = __float_as_uint(ap[0]);
                a[mi][1] = __float_as_uint(ap[8*AP2]);
                a[mi][2] = __float_as_uint(ap[4]);
                a[mi][3] = __float_as_uint(ap[8*AP2 + 4]);
            }
            const float2* bp = (const float2*)&sW[(ks*4 + tig)*BP2] + (wc0 + gid);
            #pragma unroll
            for (int nj = 0; nj < 8; nj++) {
                float2 bv = bp[nj*8];
                uint32_t b0 = __float_as_uint(bv.x);
                uint32_t b1 = __float_as_uint(bv.y);
                mma_tf32(d[0][nj], a[0], b0, b1);
                mma_tf32(d[1][nj], a[1], b0, b1);
            }
        }
    }
    __syncthreads();   // all warps done with ring before sHf overlay writes

    #pragma unroll
    for (int mi = 0; mi < 2; mi++)
        #pragma unroll
        for (int half = 0; half < 2; half++) {
            const int row = wr0 + mi*16 + gid + half*8;
            float* orow = g_h + (size_t)(row0 + row) * 128;
            #pragma unroll
            for (int nj = 0; nj < 8; nj++) {
                const int col = wc0 + nj*8 + tig*2;
                float2 res = *(float2*)(orow + col);
                float v0 = d[mi][nj][half*2 + 0] * sscale[col]     + sshift[col];
                float v1 = d[mi][nj][half*2 + 1] * sscale[col + 1] + sshift[col + 1];
                v0 = fmaxf(v0, 0.f); v1 = fmaxf(v1, 0.f);
                v0 += res.x; v1 += res.y;
                *(float2*)(orow + col) = make_float2(v0, v1);
                sHf[row*WPITCH + col]     = v0;
                sHf[row*WPITCH + col + 1] = v1;
            }
        }

    __syncthreads();
    float dt[2][4] = {};
    #pragma unroll
    for (int ks = 0; ks < 16; ks++) {
        const int kk = ks * 8;
        uint32_t a[4];
        const float* ap = sHf + (warp*16 + gid)*WPITCH + kk + tig;
        a[0] = __float_as_uint(ap[0]);
        a[1] = __float_as_uint(ap[8*WPITCH]);
        a[2] = __float_as_uint(ap[4]);
        a[3] = __float_as_uint(ap[8*WPITCH + 4]);
        #pragma unroll
        for (int nt = 0; nt < 2; nt++) {
            uint32_t b0 = __float_as_uint(sW2[(kk + tig)*TPITCH     + nt*8 + gid]);
            uint32_t b1 = __float_as_uint(sW2[(kk + tig + 4)*TPITCH + nt*8 + gid]);
            mma_tf32(dt[nt], a, b0, b1);
        }
    }
    #pragma unroll
    for (int nt = 0; nt < 2; nt++)
        #pragma unroll
        for (int half = 0; half < 2; half++) {
            const int row = warp*16 + gid + half*8;
            const int col = nt*8 + tig*2;
            float* trow = g_t + (size_t)(row0 + row) * 14;
            if (col < 14)     trow[col]     = dt[nt][half*2 + 0];
            if (col + 1 < 14) trow[col + 1] = dt[nt][half*2 + 1];
        }
}

// ================= K4: per-graph logits-agg + softmax + pooling + losses + pm =================
__global__ void k_pool(const int* __restrict__ ei, const float* __restrict__ abl) {
    __shared__ float sh[NPG * H];
    __shared__ float t1[NPG*NCL], t2[NPG*NCL], ssl[NPG*NCL], sd[NPG*NCL];
    __shared__ float adj[NPG * NPG];
    __shared__ int   se[EPG], de[EPG], degi[NPG];
    __shared__ float red[128], red2[128];
    const int g = blockIdx.x, tid = threadIdx.x;
    const float* hg = g_h + (size_t)g * NPG * H;
    for (int i = tid; i < NPG * H; i += 128) sh[i] = hg[i];
    for (int i = tid; i < NPG * 14; i += 128) {
        int n = i / 14, c = i - n*14;
        float v = g_t[(size_t)g*NPG*14 + i];
        if (c < 7) t1[n*7 + c] = v; else t2[n*7 + (c-7)] = v;
    }
    for (int i = tid; i < NPG * NPG; i += 128) adj[i] = 0.f;
    for (int i = tid; i < NPG * NCL; i += 128) ssl[i] = 0.f;
    if (tid < NPG) degi[tid] = 0;
    if (tid < EPG) {
        se[tid] = ei[(size_t)g*EPG + tid]                 - g*NPG;
        de[tid] = ei[(size_t)NEDGE + (size_t)g*EPG + tid] - g*NPG;
    }
    __syncthreads();
    if (tid < EPG) {
        atomicAdd(&degi[de[tid]], 1);
        atomicAdd(&adj[se[tid]*NPG + de[tid]], 1.f);
        #pragma unroll
        for (int c = 0; c < NCL; c++)
            atomicAdd(&ssl[de[tid]*NCL + c], t1[se[tid]*NCL + c]);
    }
    __syncthreads();
    for (int i = tid; i < NPG * NCL; i += 128) {
        int n = i / NCL;
        ssl[i] = ssl[i] / fmaxf((float)degi[n], 1.f) + t2[i] + abl[i - n*NCL];
    }
    __syncthreads();
    float ent_local = 0.f;
    if (tid < NPG) {
        float v[NCL], mx = -1e30f;
        #pragma unroll
        for (int c = 0; c < NCL; c++) { v[c] = ssl[tid*NCL + c]; mx = fmaxf(mx, v[c]); }
        float s = 0.f;
        #pragma unroll
        for (int c = 0; c < NCL; c++) { v[c] = expf(v[c] - mx); s += v[c]; }
        float inv = 1.f / s;
        #pragma unroll
        for (int c = 0; c < NCL; c++) {
            float p = v[c] * inv;
            sd[tid*NCL + c] = p;
            ent_local += -p * logf(p + 1e-15f);
        }
    }
    __syncthreads();
    float* x2g = g_x2 + (size_t)g * NCL * H;
    float pmsum = 0.f;
    #pragma unroll
    for (int c = 0; c < NCL; c++) {
        float a = 0.f;
        #pragma unroll
        for (int n = 0; n < NPG; n++) a += sd[n*NCL + c] * sh[n*128 + tid];
        x2g[c*128 + tid] = a;
        pmsum += a;
    }
    g_pm[(size_t)g*128 + tid] = pmsum * (1.f / 7.f);
    float link_local = 0.f;
    for (int p = tid; p < NPG * NPG; p += 128) {
        int n = p / NPG, m = p - NPG*n;
        float ss = 0.f;
        #pragma unroll
        for (int c = 0; c < NCL; c++) ss += sd[n*NCL + c] * sd[m*NCL + c];
        float dd = adj[p] - ss;
        link_local += dd * dd;
    }
    red[tid] = link_local; red2[tid] = ent_local;
    __syncthreads();
    for (int s = 64; s > 0; s >>= 1) {
        if (tid < s) { red[tid] += red[tid + s]; red2[tid] += red2[tid + s]; }
        __syncthreads();
    }
    if (tid == 0) { g_linkpart[g] = red[0]; g_entpart[g] = red2[0]; }
}

// ================= K5: per-graph mean of clusters (for li=3) =================
__global__ void k_pmean() {
    int idx = blockIdx.x * 256 + threadIdx.x;
    int g = idx >> 7, col = idx & 127;
    const float* xg = g_x2 + (size_t)g * NCL * H + col;
    float a = 0.f;
    #pragma unroll
    for (int c = 0; c < NCL; c++) a += xg[c * 128];
    g_pm[idx] = a * (1.f / 7.f);
}

// ================= K6: readout =================
__global__ void k_readout(const float* __restrict__ linW, const float* __restrict__ linb,
                          float* __restrict__ out) {
    const int g = blockIdx.x, tid = threadIdx.x;
    const float* xg = g_x2 + (size_t)g * NCL * H;
    float v = 0.f;
    #pragma unroll
    for (int c = 0; c < NCL; c++) v += xg[c * 128 + tid];
    v *= (1.f / 7.f);
    __shared__ float red[128];
    red[tid] = v * linW[tid];
    __syncthreads();
    for (int s = 64; s > 0; s >>= 1) {
        if (tid < s) red[tid] += red[tid + s];
        __syncthreads();
    }
    if (tid == 0) out[g] = 1.f / (1.f + expf(-(red[0] + linb[0])));
}

// ================= K7: deterministic loss reduction =================
__global__ void k_reduce(float* __restrict__ out) {
    __shared__ float s1[1024], s2[1024];
    const int tid = threadIdx.x;
    float a = 0.f, b = 0.f;
    for (int i = tid; i < NB; i += 1024) { a += g_linkpart[i]; b += g_entpart[i]; }
    s1[tid] = a; s2[tid] = b;
    __syncthreads();
    for (int s = 512; s > 0; s >>= 1) {
        if (tid < s) { s1[tid] += s1[tid + s]; s2[tid] += s2[tid + s]; }
        __syncthreads();
    }
    if (tid == 0) {
        out[NB]     = sqrtf(s1[0]) / 11075584.f;
        out[NB + 1] = s2[0] / (float)NTOT;
    }
}

extern "C" void kernel_launch(void* const* d_in, const int* in_sizes, int n_in,
                              void* d_out, int out_size) {
    (void)in_sizes; (void)n_in; (void)out_size;
    const int*   x    = (const int*)  d_in[0];
    const int*   ei   = (const int*)  d_in[1];
    const float* emb  = (const float*)d_in[3];
    const float* cWl  = (const float*)d_in[4];
    const float* cbl  = (const float*)d_in[5];
    const float* cWr  = (const float*)d_in[6];
    const float* bng  = (const float*)d_in[7];
    const float* bnb  = (const float*)d_in[8];
    const float* bnm  = (const float*)d_in[9];
    const float* bnv  = (const float*)d_in[10];
    const float* aWl  = (const float*)d_in[11];
    const float* abl  = (const float*)d_in[12];
    const float* aWr  = (const float*)d_in[13];
    const float* linW = (const float*)d_in[14];
    const float* linb = (const float*)d_in[15];
    float* out = (float*)d_out;

    float* wp;
    cudaGetSymbolAddress((void**)&wp, g_wp);

    const int pipe_smem = PIPE_FLOATS * 4;   // 105984
    cudaFuncSetAttribute(k_gemm_pipe<1,0>, cudaFuncAttributeMaxDynamicSharedMemorySize, pipe_smem);
    cudaFuncSetAttribute(k_gemm_pipe<0,1>, cudaFuncAttributeMaxDynamicSharedMemorySize, pipe_smem);
    cudaFuncSetAttribute(k_gemm_pipeT, cudaFuncAttributeMaxDynamicSharedMemorySize, pipe_smem);

    k_wt<<<4*32768/256, 256>>>(cWl, cWr);

    // layer 0 (encoder fused with aggregation)
    k_encagg<<<NB, 128>>>(x, emb, ei);
    k_gemm_pipe<1,0><<<NTOT / 128, 256, pipe_smem>>>(
        wp, cbl, bng, bnb, bnm, bnv);
    // layer 1 (+ fused T = h@[aWl|aWr])
    k_agg2<<<NB, 128>>>(ei);
    k_gemm_pipeT<<<NTOT / 128, 256, pipe_smem>>>(
        wp + 32768, cbl + 128,
        bng + 128, bnb + 128, bnm + 128, bnv + 128, aWl, aWr);

    k_pool<<<NB, 128>>>(ei, abl);     // also writes g_pm (first pmean fused)

    // pooled layer 2
    k_gemm_pipe<0,1><<<NB * NCL / 128, 256, pipe_smem>>>(
        wp + 2*32768, cbl + 2*128,
        bng + 2*128, bnb + 2*128, bnm + 2*128, bnv + 2*128);
    // pooled layer 3
    k_pmean<<<NB * 128 / 256, 256>>>();
    k_gemm_pipe<0,1><<<NB * NCL / 128, 256, pipe_smem>>>(
        wp + 3*32768, cbl + 3*128,
        bng + 3*128, bnb + 3*128, bnm + 3*128, bnv + 3*128);

    k_readout<<<NB, 128>>>(linW, linb, out);
    k_reduce<<<1, 1024>>>(out);
}

// round 16
// speedup vs baseline: 1.2956x; 1.1566x over previous
#include <cuda_runtime.h>
#include <math.h>
#include <stdint.h>

#define H     128
#define NB    16384
#define NPG   26
#define EPG   52
#define NCL   7
#define NTOT  (NB*NPG)      // 425984
#define NEDGE (NB*EPG)      // 851968

// ------------- scratch: device globals (no runtime allocation) -------------
__device__ float g_h[NTOT*H];
__device__ float g_mean[NTOT*H];
__device__ float g_t[NTOT*14];
__device__ float g_x2[NB*NCL*H];
__device__ float g_pm[NB*H];
__device__ float g_linkpart[NB];
__device__ float g_entpart[NB];
__device__ float g_wp[4*256*128];    // permuted [Wl;Wr] per layer (see k_wt)

// ---- cp.async helpers ----
#define CP_ASYNC16(dst, src) \
    asm volatile("cp.async.cg.shared.global [%0], [%1], 16;\n" :: "r"(dst), "l"(src))
#define CP_COMMIT() asm volatile("cp.async.commit_group;\n" ::: "memory")
#define CP_WAIT(n)  asm volatile("cp.async.wait_group %0;\n" :: "n"(n) : "memory")

// ================= K0: one-time weight permute =================
__global__ void k_wt(const float* __restrict__ cWl, const float* __restrict__ cWr) {
    int idx = blockIdx.x * 256 + threadIdx.x;      // 4*32768 total
    int li = idx >> 15, rem = idx & 32767;
    int k = rem >> 7, n = rem & 127;
    float v = (k < 128) ? cWl[li*16384 + k*128 + n]
                        : cWr[li*16384 + (k-128)*128 + n];
    int kb = k >> 3, h = (k >> 2) & 1, p = k & 3;
    g_wp[li*32768 + (((kb*4 + p)*128) + n)*2 + h] = v;
}

// ================= K1: fused atom encoder + layer-0 neighbor mean =================
__global__ __launch_bounds__(128)
void k_encagg(const int* __restrict__ x, const float* __restrict__ emb,
              const int* __restrict__ ei) {
    __shared__ float sh[NPG * H];
    __shared__ int   sx[NPG * 9];
    __shared__ int   se[EPG], sde[EPG], sdeg[NPG], sstart[NPG+1], soffs[NPG], ssrt[EPG];
    __shared__ int   soff2[EPG], swd[EPG];
    __shared__ float srdeg[NPG];
    const int g = blockIdx.x, tid = threadIdx.x;
    for (int i = tid; i < NPG*9; i += 128) sx[i] = x[(size_t)g*NPG*9 + i];
    if (tid < NPG) sdeg[tid] = 0;
    if (tid < EPG) {
        se[tid]  = ei[(size_t)g*EPG + tid]                 - g*NPG;
        sde[tid] = ei[(size_t)NEDGE + (size_t)g*EPG + tid] - g*NPG;
        swd[tid] = -1;
    }
    __syncthreads();
    if (tid < EPG) atomicAdd(&sdeg[sde[tid]], 1);
    __syncthreads();
    if (tid == 0) {
        int acc = 0;
        #pragma unroll
        for (int n = 0; n < NPG; n++) { sstart[n] = acc; acc += sdeg[n]; }
        sstart[NPG] = acc;
    }
    if (tid < NPG) srdeg[tid] = 1.f / fmaxf((float)sdeg[tid], 1.f);
    __syncthreads();
    if (tid < NPG) soffs[tid] = sstart[tid];
    __syncthreads();
    if (tid < EPG) {
        int pos = atomicAdd(&soffs[sde[tid]], 1);
        ssrt[pos] = se[tid];
    }
    if (tid < NPG && sdeg[tid] > 0) swd[sstart[tid+1] - 1] = tid;
    // embedding gather: 2 nodes per iteration (independent chains -> 2x MLP)
    float* hg = g_h + (size_t)g * NPG * H;
    for (int n = 0; n < NPG; n += 2) {
        float acc0 = 0.f, acc1 = 0.f;
        #pragma unroll
        for (int f = 0; f < 9; f++) {
            int v0 = sx[n*9 + f];
            int v1 = sx[(n+1)*9 + f];
            acc0 += __ldg(&emb[((size_t)f*119 + v0)*128 + tid]);
            acc1 += __ldg(&emb[((size_t)f*119 + v1)*128 + tid]);
        }
        sh[n*H + tid]       = acc0;
        sh[(n+1)*H + tid]   = acc1;
        hg[(size_t)n*H + tid]     = acc0;
        hg[(size_t)(n+1)*H + tid] = acc1;
    }
    __syncthreads();
    if (tid < EPG) soff2[tid] = ssrt[tid] * H;
    __syncthreads();
    float* mg = g_mean + (size_t)g * NPG * H;
    const int c = tid;
    float acc = 0.f;
    #pragma unroll 4
    for (int j = 0; j < EPG; j++) {
        acc += sh[soff2[j] + c];
        int w = swd[j];
        if (w >= 0) { mg[(size_t)w*H + c] = acc * srdeg[w]; acc = 0.f; }
    }
    #pragma unroll
    for (int n = 0; n < NPG; n++)
        if (sdeg[n] == 0) mg[(size_t)n*H + c] = 0.f;
}

// ================= K2: neighbor-mean via segmented-scan CSR =================
__global__ __launch_bounds__(128)
void k_agg2(const int* __restrict__ ei) {
    __shared__ float sh[NPG * H];
    __shared__ int   se[EPG], sde[EPG], sdeg[NPG], sstart[NPG+1], soffs[NPG], ssrt[EPG];
    __shared__ int   soff2[EPG], swd[EPG];
    __shared__ float srdeg[NPG];
    const int g = blockIdx.x, tid = threadIdx.x;
    const float* hg = g_h + (size_t)g * NPG * H;
    for (int i = tid; i < NPG*32; i += 128)
        *(float4*)&sh[i*4] = *(const float4*)(hg + (size_t)i*4);
    if (tid < NPG) sdeg[tid] = 0;
    if (tid < EPG) swd[tid] = -1;
    __syncthreads();
    if (tid < EPG) {
        int s = ei[(size_t)g*EPG + tid]                 - g*NPG;
        int d = ei[(size_t)NEDGE + (size_t)g*EPG + tid] - g*NPG;
        se[tid] = s; sde[tid] = d;
        atomicAdd(&sdeg[d], 1);
    }
    __syncthreads();
    if (tid == 0) {
        int acc = 0;
        #pragma unroll
        for (int n = 0; n < NPG; n++) { sstart[n] = acc; acc += sdeg[n]; }
        sstart[NPG] = acc;
    }
    if (tid < NPG) srdeg[tid] = 1.f / fmaxf((float)sdeg[tid], 1.f);
    __syncthreads();
    if (tid < NPG) soffs[tid] = sstart[tid];
    __syncthreads();
    if (tid < EPG) {
        int pos = atomicAdd(&soffs[sde[tid]], 1);
        ssrt[pos] = se[tid];
    }
    if (tid < NPG && sdeg[tid] > 0) swd[sstart[tid+1] - 1] = tid;
    __syncthreads();
    if (tid < EPG) soff2[tid] = ssrt[tid] * H;
    __syncthreads();
    float* mg = g_mean + (size_t)g * NPG * H;
    const int c = tid;
    float acc = 0.f;
    #pragma unroll 4
    for (int j = 0; j < EPG; j++) {
        acc += sh[soff2[j] + c];
        int w = swd[j];
        if (w >= 0) { mg[(size_t)w*H + c] = acc * srdeg[w]; acc = 0.f; }
    }
    #pragma unroll
    for (int n = 0; n < NPG; n++)
        if (sdeg[n] == 0) mg[(size_t)n*H + c] = 0.f;
}

// ================= tf32 mma.sync helper (verified layout) =================
__device__ __forceinline__ void mma_tf32(float* d, const uint32_t* a,
                                         uint32_t b0, uint32_t b1) {
    asm volatile(
        "mma.sync.aligned.m16n8k8.row.col.f32.tf32.tf32.f32 "
        "{%0,%1,%2,%3}, {%4,%5,%6,%7}, {%8,%9}, {%0,%1,%2,%3};\n"
        : "+f"(d[0]), "+f"(d[1]), "+f"(d[2]), "+f"(d[3])
        : "r"(a[0]), "r"(a[1]), "r"(a[2]), "r"(a[3]), "r"(b0), "r"(b1));
}

#define WPITCH 132
#define TPITCH 17
#define BP2    264
#define AP2    36
#define STAGEF (16*BP2 + 128*AP2)       // 8832 floats / stage
#define PIPE_FLOATS (3*STAGEF)          // 105984 B

// ================= K3a: 3-stage pipelined GEMM, permuted-W LDS64 b-frags =================
template<int RELU, int POOLED>
__global__ __launch_bounds__(256, 2)
void k_gemm_pipe(const float* __restrict__ wp,
                 const float* __restrict__ bl,
                 const float* __restrict__ bng, const float* __restrict__ bnb,
                 const float* __restrict__ bnm, const float* __restrict__ bnv)
{
    extern __shared__ float smem[];
    __shared__ float sscale[128], sshift[128];

    const int tid  = threadIdx.x;
    const int row0 = blockIdx.x * 128;
    const float* Am = POOLED ? g_pm : g_mean;
    float*       Ah = POOLED ? g_x2 : g_h;

    if (tid < 128) {
        float sc = bng[tid] * rsqrtf(bnv[tid] + 1e-5f);
        sscale[tid] = sc;
        sshift[tid] = bnb[tid] + sc * (bl[tid] - bnm[tid]);
    }

    const int lane = tid & 31, warp = tid >> 5;
    const int gid = lane >> 2, tig = lane & 3;
    const int wr0 = (warp & 3) * 32;
    const int wc0 = (warp >> 2) * 64;
    float d[2][8][4] = {};

    auto issue = [&](int ch, float* stage) {
        float* sW = stage;
        float* sA = stage + 16*BP2;
        #pragma unroll
        for (int v = 0; v < 4; v++) {
            int i  = tid + v*256;
            int r  = i >> 3, c4 = (i & 7) * 4;
            int gk = ch*32 + c4;
            int grow = row0 + r;
            const float* ap;
            if (gk < 128) {
                int mrow = POOLED ? (grow / 7) : grow;
                ap = Am + (size_t)mrow*128 + gk;
            } else {
                ap = Ah + (size_t)grow*128 + (gk - 128);
            }
            uint32_t dst = (uint32_t)__cvta_generic_to_shared(&sA[r*AP2 + c4]);
            CP_ASYNC16(dst, ap);
        }
        #pragma unroll
        for (int v = 0; v < 4; v++) {
            int i  = tid + v*256;
            int r  = i >> 6, c4 = (i & 63) * 4;
            const float* src = wp + (size_t)(ch*16 + r)*256 + c4;
            uint32_t dst = (uint32_t)__cvta_generic_to_shared(&sW[r*BP2 + c4]);
            CP_ASYNC16(dst, src);
        }
        CP_COMMIT();
    };

    issue(0, smem);
    issue(1, smem + STAGEF);
    #pragma unroll
    for (int ch = 0; ch < 8; ch++) {
        if (ch < 7) { CP_WAIT(1); } else { CP_WAIT(0); }
        __syncthreads();
        if (ch < 6) issue(ch + 2, smem + ((ch + 2) % 3) * STAGEF);
        const float* stage = smem + (ch % 3) * STAGEF;
        const float* sW = stage;
        const float* sA = stage + 16*BP2;
        #pragma unroll
        for (int ks = 0; ks < 4; ks++) {
            const int kk = ks * 8;
            uint32_t a[2][4];
            #pragma unroll
            for (int mi = 0; mi < 2; mi++) {
                const float* ap = sA + (wr0 + mi*16 + gid)*AP2 + kk + tig;
                a[mi][0] = __float_as_uint(ap[0]);
                a[mi][1] = __float_as_uint(ap[8*AP2]);
                a[mi][2] = __float_as_uint(ap[4]);
                a[mi][3] = __float_as_uint(ap[8*AP2 + 4]);
            }
            const float2* bp = (const float2*)&sW[(ks*4 + tig)*BP2] + (wc0 + gid);
            #pragma unroll
            for (int nj = 0; nj < 8; nj++) {
                float2 bv = bp[nj*8];
                uint32_t b0 = __float_as_uint(bv.x);
                uint32_t b1 = __float_as_uint(bv.y);
                mma_tf32(d[0][nj], a[0], b0, b1);
                mma_tf32(d[1][nj], a[1], b0, b1);
            }
        }
    }

    #pragma unroll
    for (int mi = 0; mi < 2; mi++)
        #pragma unroll
        for (int half = 0; half < 2; half++) {
            const int row = wr0 + mi*16 + gid + half*8;
            float* orow = Ah + (size_t)(row0 + row) * 128;
            #pragma unroll
            for (int nj = 0; nj < 8; nj++) {
                const int col = wc0 + nj*8 + tig*2;
                float2 res = *(float2*)(orow + col);
                float v0 = d[mi][nj][half*2 + 0] * sscale[col]     + sshift[col];
                float v1 = d[mi][nj][half*2 + 1] * sscale[col + 1] + sshift[col + 1];
                if (RELU) { v0 = fmaxf(v0, 0.f); v1 = fmaxf(v1, 0.f); }
                *(float2*)(orow + col) = make_float2(v0 + res.x, v1 + res.y);
            }
        }
}

// ================= K3b: 3-stage pipelined GEMM + fused T epilogue (li=1) =================
__global__ __launch_bounds__(256, 2)
void k_gemm_pipeT(const float* __restrict__ wp,
                  const float* __restrict__ bl,
                  const float* __restrict__ bng, const float* __restrict__ bnb,
                  const float* __restrict__ bnm, const float* __restrict__ bnv,
                  const float* __restrict__ aWl, const float* __restrict__ aWr)
{
    extern __shared__ float smem[];
    float* sHf = smem;
    __shared__ float sscale[128], sshift[128];
    __shared__ float sW2[128*TPITCH];

    const int tid  = threadIdx.x;
    const int row0 = blockIdx.x * 128;

    if (tid < 128) {
        float sc = bng[tid] * rsqrtf(bnv[tid] + 1e-5f);
        sscale[tid] = sc;
        sshift[tid] = bnb[tid] + sc * (bl[tid] - bnm[tid]);
    }
    for (int i = tid; i < 128*16; i += 256) {
        int k = i >> 4, c = i & 15;
        float v = 0.f;
        if (c < 7)       v = aWl[k*NCL + c];
        else if (c < 14) v = aWr[k*NCL + (c - 7)];
        sW2[k*TPITCH + c] = v;
    }

    const int lane = tid & 31, warp = tid >> 5;
    const int gid = lane >> 2, tig = lane & 3;
    const int wr0 = (warp & 3) * 32;
    const int wc0 = (warp >> 2) * 64;
    float d[2][8][4] = {};

    auto issue = [&](int ch, float* stage) {
        float* sW = stage;
        float* sA = stage + 16*BP2;
        #pragma unroll
        for (int v = 0; v < 4; v++) {
            int i  = tid + v*256;
            int r  = i >> 3, c4 = (i & 7) * 4;
            int gk = ch*32 + c4;
            int grow = row0 + r;
            const float* ap = (gk < 128) ? (g_mean + (size_t)grow*128 + gk)
                                         : (g_h    + (size_t)grow*128 + (gk - 128));
            uint32_t dst = (uint32_t)__cvta_generic_to_shared(&sA[r*AP2 + c4]);
            CP_ASYNC16(dst, ap);
        }
        #pragma unroll
        for (int v = 0; v < 4; v++) {
            int i  = tid + v*256;
            int r  = i >> 6, c4 = (i & 63) * 4;
            const float* src = wp + (size_t)(ch*16 + r)*256 + c4;
            uint32_t dst = (uint32_t)__cvta_generic_to_shared(&sW[r*BP2 + c4]);
            CP_ASYNC16(dst, src);
        }
        CP_COMMIT();
    };

    issue(0, smem);
    issue(1, smem + STAGEF);
    #pragma unroll
    for (int ch = 0; ch < 8; ch++) {
        if (ch < 7) { CP_WAIT(1); } else { CP_WAIT(0); }
        __syncthreads();
        if (ch < 6) issue(ch + 2, smem + ((ch + 2) % 3) * STAGEF);
        const float* stage = smem + (ch % 3) * STAGEF;
        const float* sW = stage;
        const float* sA = stage + 16*BP2;
        #pragma unroll
        for (int ks = 0; ks < 4; ks++) {
            const int kk = ks * 8;
            uint32_t a[2][4];
            #pragma unroll
            for (int mi = 0; mi < 2; mi++) {
                const float* ap = sA + (wr0 + mi*16 + gid)*AP2 + kk + tig;
                a[mi][0] = __float_as_uint(ap[0]);
                a[mi][1] = __float_as_uint(ap[8*AP2]);
                a[mi][2] = __float_as_uint(ap[4]);
                a[mi][3] = __float_as_uint(ap[8*AP2 + 4]);
            }
            const float2* bp = (const float2*)&sW[(ks*4 + tig)*BP2] + (wc0 + gid);
            #pragma unroll
            for (int nj = 0; nj < 8; nj++) {
                float2 bv = bp[nj*8];
                uint32_t b0 = __float_as_uint(bv.x);
                uint32_t b1 = __float_as_uint(bv.y);
                mma_tf32(d[0][nj], a[0], b0, b1);
                mma_tf32(d[1][nj], a[1], b0, b1);
            }
        }
    }
    __syncthreads();   // all warps done with ring before sHf overlay writes

    #pragma unroll
    for (int mi = 0; mi < 2; mi++)
        #pragma unroll
        for (int half = 0; half < 2; half++) {
            const int row = wr0 + mi*16 + gid + half*8;
            float* orow = g_h + (size_t)(row0 + row) * 128;
            #pragma unroll
            for (int nj = 0; nj < 8; nj++) {
                const int col = wc0 + nj*8 + tig*2;
                float2 res = *(float2*)(orow + col);
                float v0 = d[mi][nj][half*2 + 0] * sscale[col]     + sshift[col];
                float v1 = d[mi][nj][half*2 + 1] * sscale[col + 1] + sshift[col + 1];
                v0 = fmaxf(v0, 0.f); v1 = fmaxf(v1, 0.f);
                v0 += res.x; v1 += res.y;
                *(float2*)(orow + col) = make_float2(v0, v1);
                sHf[row*WPITCH + col]     = v0;
                sHf[row*WPITCH + col + 1] = v1;
            }
        }

    __syncthreads();
    float dt[2][4] = {};
    #pragma unroll
    for (int ks = 0; ks < 16; ks++) {
        const int kk = ks * 8;
        uint32_t a[4];
        const float* ap = sHf + (warp*16 + gid)*WPITCH + kk + tig;
        a[0] = __float_as_uint(ap[0]);
        a[1] = __float_as_uint(ap[8*WPITCH]);
        a[2] = __float_as_uint(ap[4]);
        a[3] = __float_as_uint(ap[8*WPITCH + 4]);
        #pragma unroll
        for (int nt = 0; nt < 2; nt++) {
            uint32_t b0 = __float_as_uint(sW2[(kk + tig)*TPITCH     + nt*8 + gid]);
            uint32_t b1 = __float_as_uint(sW2[(kk + tig + 4)*TPITCH + nt*8 + gid]);
            mma_tf32(dt[nt], a, b0, b1);
        }
    }
    #pragma unroll
    for (int nt = 0; nt < 2; nt++)
        #pragma unroll
        for (int half = 0; half < 2; half++) {
            const int row = warp*16 + gid + half*8;
            const int col = nt*8 + tig*2;
            float* trow = g_t + (size_t)(row0 + row) * 14;
            if (col < 14)     trow[col]     = dt[nt][half*2 + 0];
            if (col + 1 < 14) trow[col + 1] = dt[nt][half*2 + 1];
        }
}

// ================= K4: per-graph logits-agg + softmax + pooling + losses + pm =================
__global__ void k_pool(const int* __restrict__ ei, const float* __restrict__ abl) {
    __shared__ float sh[NPG * H];
    __shared__ float t1[NPG*NCL], t2[NPG*NCL], ssl[NPG*NCL], sd[NPG*NCL];
    __shared__ float adj[NPG * NPG];
    __shared__ int   se[EPG], de[EPG], degi[NPG];
    __shared__ float red[128], red2[128];
    const int g = blockIdx.x, tid = threadIdx.x;
    const float* hg = g_h + (size_t)g * NPG * H;
    for (int i = tid; i < NPG * H; i += 128) sh[i] = hg[i];
    for (int i = tid; i < NPG * 14; i += 128) {
        int n = i / 14, c = i - n*14;
        float v = g_t[(size_t)g*NPG*14 + i];
        if (c < 7) t1[n*7 + c] = v; else t2[n*7 + (c-7)] = v;
    }
    for (int i = tid; i < NPG * NPG; i += 128) adj[i] = 0.f;
    for (int i = tid; i < NPG * NCL; i += 128) ssl[i] = 0.f;
    if (tid < NPG) degi[tid] = 0;
    if (tid < EPG) {
        se[tid] = ei[(size_t)g*EPG + tid]                 - g*NPG;
        de[tid] = ei[(size_t)NEDGE + (size_t)g*EPG + tid] - g*NPG;
    }
    __syncthreads();
    if (tid < EPG) {
        atomicAdd(&degi[de[tid]], 1);
        atomicAdd(&adj[se[tid]*NPG + de[tid]], 1.f);
        #pragma unroll
        for (int c = 0; c < NCL; c++)
            atomicAdd(&ssl[de[tid]*NCL + c], t1[se[tid]*NCL + c]);
    }
    __syncthreads();
    for (int i = tid; i < NPG * NCL; i += 128) {
        int n = i / NCL;
        ssl[i] = ssl[i] / fmaxf((float)degi[n], 1.f) + t2[i] + abl[i - n*NCL];
    }
    __syncthreads();
    float ent_local = 0.f;
    if (tid < NPG) {
        float v[NCL], mx = -1e30f;
        #pragma unroll
        for (int c = 0; c < NCL; c++) { v[c] = ssl[tid*NCL + c]; mx = fmaxf(mx, v[c]); }
        float s = 0.f;
        #pragma unroll
        for (int c = 0; c < NCL; c++) { v[c] = expf(v[c] - mx); s += v[c]; }
        float inv = 1.f / s;
        #pragma unroll
        for (int c = 0; c < NCL; c++) {
            float p = v[c] * inv;
            sd[tid*NCL + c] = p;
            ent_local += -p * logf(p + 1e-15f);
        }
    }
    __syncthreads();
    // x2: register accumulators, one sh load per node (order per column unchanged)
    float* x2g = g_x2 + (size_t)g * NCL * H;
    float accs[NCL];
    #pragma unroll
    for (int c = 0; c < NCL; c++) accs[c] = 0.f;
    #pragma unroll 2
    for (int n = 0; n < NPG; n++) {
        float hv = sh[n*128 + tid];
        #pragma unroll
        for (int c = 0; c < NCL; c++) accs[c] += sd[n*NCL + c] * hv;
    }
    float pmsum = 0.f;
    #pragma unroll
    for (int c = 0; c < NCL; c++) { x2g[c*128 + tid] = accs[c]; pmsum += accs[c]; }
    g_pm[(size_t)g*128 + tid] = pmsum * (1.f / 7.f);
    float link_local = 0.f;
    for (int p = tid; p < NPG * NPG; p += 128) {
        int n = p / NPG, m = p - NPG*n;
        float ss = 0.f;
        #pragma unroll
        for (int c = 0; c < NCL; c++) ss += sd[n*NCL + c] * sd[m*NCL + c];
        float dd = adj[p] - ss;
        link_local += dd * dd;
    }
    red[tid] = link_local; red2[tid] = ent_local;
    __syncthreads();
    for (int s = 64; s > 0; s >>= 1) {
        if (tid < s) { red[tid] += red[tid + s]; red2[tid] += red2[tid + s]; }
        __syncthreads();
    }
    if (tid == 0) { g_linkpart[g] = red[0]; g_entpart[g] = red2[0]; }
}

// ================= K5: per-graph mean of clusters (for li=3) =================
__global__ void k_pmean() {
    int idx = blockIdx.x * 256 + threadIdx.x;
    int g = idx >> 7, col = idx & 127;
    const float* xg = g_x2 + (size_t)g * NCL * H + col;
    float a = 0.f;
    #pragma unroll
    for (int c = 0; c < NCL; c++) a += xg[c * 128];
    g_pm[idx] = a * (1.f / 7.f);
}

// ================= K6: readout =================
__global__ void k_readout(const float* __restrict__ linW, const float* __restrict__ linb,
                          float* __restrict__ out) {
    const int g = blockIdx.x, tid = threadIdx.x;
    const float* xg = g_x2 + (size_t)g * NCL * H;
    float v = 0.f;
    #pragma unroll
    for (int c = 0; c < NCL; c++) v += xg[c * 128 + tid];
    v *= (1.f / 7.f);
    __shared__ float red[128];
    red[tid] = v * linW[tid];
    __syncthreads();
    for (int s = 64; s > 0; s >>= 1) {
        if (tid < s) red[tid] += red[tid + s];
        __syncthreads();
    }
    if (tid == 0) out[g] = 1.f / (1.f + expf(-(red[0] + linb[0])));
}

// ================= K7: deterministic loss reduction =================
__global__ void k_reduce(float* __restrict__ out) {
    __shared__ float s1[1024], s2[1024];
    const int tid = threadIdx.x;
    float a = 0.f, b = 0.f;
    for (int i = tid; i < NB; i += 1024) { a += g_linkpart[i]; b += g_entpart[i]; }
    s1[tid] = a; s2[tid] = b;
    __syncthreads();
    for (int s = 512; s > 0; s >>= 1) {
        if (tid < s) { s1[tid] += s1[tid + s]; s2[tid] += s2[tid + s]; }
        __syncthreads();
    }
    if (tid == 0) {
        out[NB]     = sqrtf(s1[0]) / 11075584.f;
        out[NB + 1] = s2[0] / (float)NTOT;
    }
}

extern "C" void kernel_launch(void* const* d_in, const int* in_sizes, int n_in,
                              void* d_out, int out_size) {
    (void)in_sizes; (void)n_in; (void)out_size;
    const int*   x    = (const int*)  d_in[0];
    const int*   ei   = (const int*)  d_in[1];
    const float* emb  = (const float*)d_in[3];
    const float* cWl  = (const float*)d_in[4];
    const float* cbl  = (const float*)d_in[5];
    const float* cWr  = (const float*)d_in[6];
    const float* bng  = (const float*)d_in[7];
    const float* bnb  = (const float*)d_in[8];
    const float* bnm  = (const float*)d_in[9];
    const float* bnv  = (const float*)d_in[10];
    const float* aWl  = (const float*)d_in[11];
    const float* abl  = (const float*)d_in[12];
    const float* aWr  = (const float*)d_in[13];
    const float* linW = (const float*)d_in[14];
    const float* linb = (const float*)d_in[15];
    float* out = (float*)d_out;

    float* wp;
    cudaGetSymbolAddress((void**)&wp, g_wp);

    const int pipe_smem = PIPE_FLOATS * 4;   // 105984
    cudaFuncSetAttribute(k_gemm_pipe<1,0>, cudaFuncAttributeMaxDynamicSharedMemorySize, pipe_smem);
    cudaFuncSetAttribute(k_gemm_pipe<0,1>, cudaFuncAttributeMaxDynamicSharedMemorySize, pipe_smem);
    cudaFuncSetAttribute(k_gemm_pipeT, cudaFuncAttributeMaxDynamicSharedMemorySize, pipe_smem);

    k_wt<<<4*32768/256, 256>>>(cWl, cWr);

    // layer 0 (encoder fused with aggregation)
    k_encagg<<<NB, 128>>>(x, emb, ei);
    k_gemm_pipe<1,0><<<NTOT / 128, 256, pipe_smem>>>(
        wp, cbl, bng, bnb, bnm, bnv);
    // layer 1 (+ fused T = h@[aWl|aWr])
    k_agg2<<<NB, 128>>>(ei);
    k_gemm_pipeT<<<NTOT / 128, 256, pipe_smem>>>(
        wp + 32768, cbl + 128,
        bng + 128, bnb + 128, bnm + 128, bnv + 128, aWl, aWr);

    k_pool<<<NB, 128>>>(ei, abl);     // also writes g_pm (first pmean fused)

    // pooled layer 2
    k_gemm_pipe<0,1><<<NB * NCL / 128, 256, pipe_smem>>>(
        wp + 2*32768, cbl + 2*128,
        bng + 2*128, bnb + 2*128, bnm + 2*128, bnv + 2*128);
    // pooled layer 3
    k_pmean<<<NB * 128 / 256, 256>>>();
    k_gemm_pipe<0,1><<<NB * NCL / 128, 256, pipe_smem>>>(
        wp + 3*32768, cbl + 3*128,
        bng + 3*128, bnb + 3*128, bnm + 3*128, bnv + 3*128);

    k_readout<<<NB, 128>>>(linW, linb, out);
    k_reduce<<<1, 1024>>>(out);
}